// round 1
// baseline (speedup 1.0000x reference)
#include <cuda_runtime.h>
#include <math.h>

// ---------------------------------------------------------------------------
// CSTreeLSTM: 16-ary tree, depth 4 (levels 0..4), IN=HID=512.
// Level sizes: 1,16,256,4096,65536 ; offsets 0,1,17,273,4369 ; total 69905.
//
// Decomposition:
//   leaves:  G = X_leaf @ Wleaf^T + bleaf           (Wleaf = x-cols of wi,wo,wu)
//            C = sig(i)*tanh(u); H = sig(o)*tanh(C)
//            FH = C @ Wfh^T                          (Wfh = h-cols of wf)
//   level d: XH = [X_d, sum_k H_child]
//            G = XH @ Wnode^T + bnode               (rows: i,o,u full; fx = x-cols of wf, h-cols zero; b_f folded into fx)
//            C = i*u + sum_k sig(fx + FH_child_k) * C_child_k ; H = o*tanh(C)
//            FH = C @ Wfh^T (skip at root)
// Output: H[0] (512) then C[0] (512).
// ---------------------------------------------------------------------------

#define IN_DIM 512
#define HID    512
#define NLEAF  65536
#define NTOT   69905

// scratch (device globals: no allocation allowed)
__device__ float g_C [NTOT * HID];
__device__ float g_H [NTOT * HID];
__device__ float g_FH[NTOT * HID];
__device__ float g_G [NLEAF * 1536];        // gates buffer (largest use: leaf 65536x1536)
__device__ float g_XH[4096 * 1024];         // concat buffer for internal levels
__device__ float g_Wleaf[1536 * IN_DIM];
__device__ float g_bleaf[1536];
__device__ float g_Wnode[2048 * 1024];
__device__ float g_bnode[2048];
__device__ float g_Wfh[HID * HID];

__device__ __forceinline__ float sigf(float x) { return 1.f / (1.f + expf(-x)); }

// ---------------------------------------------------------------------------
// Weight packing
// ---------------------------------------------------------------------------
__global__ void pack_weights(const float* __restrict__ wi_w, const float* __restrict__ wi_b,
                             const float* __restrict__ wf_w, const float* __restrict__ wf_b,
                             const float* __restrict__ wo_w, const float* __restrict__ wo_b,
                             const float* __restrict__ wu_w, const float* __restrict__ wu_b) {
    int idx = blockIdx.x * blockDim.x + threadIdx.x;

    if (idx < 2048 * 1024) {                     // Wnode [2048][1024]
        int r = idx >> 10, k = idx & 1023;
        float v;
        if      (r <  512) v = wi_w[r * 1024 + k];
        else if (r < 1024) v = wo_w[(r -  512) * 1024 + k];
        else if (r < 1536) v = wu_w[(r - 1024) * 1024 + k];
        else               v = (k < 512) ? wf_w[(r - 1536) * 1024 + k] : 0.f;
        g_Wnode[idx] = v;
    }
    if (idx < 1536 * 512) {                      // Wleaf [1536][512] (x-cols only)
        int r = idx >> 9, k = idx & 511;
        float v;
        if      (r <  512) v = wi_w[r * 1024 + k];
        else if (r < 1024) v = wo_w[(r -  512) * 1024 + k];
        else               v = wu_w[(r - 1024) * 1024 + k];
        g_Wleaf[idx] = v;
    }
    if (idx < 512 * 512) {                       // Wfh [512][512] (h-cols of wf)
        int r = idx >> 9, k = idx & 511;
        g_Wfh[idx] = wf_w[r * 1024 + 512 + k];
    }
    if (idx < 1536) {
        g_bleaf[idx] = (idx < 512) ? wi_b[idx]
                     : (idx < 1024) ? wo_b[idx - 512]
                                    : wu_b[idx - 1024];
    }
    if (idx < 2048) {
        g_bnode[idx] = (idx <  512) ? wi_b[idx]
                     : (idx < 1024) ? wo_b[idx -  512]
                     : (idx < 1536) ? wu_b[idx - 1024]
                                    : wf_b[idx - 1536];
    }
}

// ---------------------------------------------------------------------------
// SGEMM: C[M,N] = A[M,K] * B[N,K]^T (+ bias[N]).  BM=BN=128, BK=8,
// 256 threads, 8x8 per thread. N%128==0, K%8==0 guaranteed; M guarded.
// ---------------------------------------------------------------------------
__global__ __launch_bounds__(256, 2)
void sgemm(const float* __restrict__ A, const float* __restrict__ B,
           float* __restrict__ C, const float* __restrict__ bias,
           int M, int N, int K) {
    __shared__ float As[8][128];
    __shared__ float Bs[8][128];

    const int tid = threadIdx.x;
    const int tx  = tid & 15;        // 0..15  -> N
    const int ty  = tid >> 4;        // 0..15  -> M
    const int bm  = blockIdx.y * 128;
    const int bn  = blockIdx.x * 128;

    float acc[8][8];
#pragma unroll
    for (int i = 0; i < 8; i++)
#pragma unroll
        for (int j = 0; j < 8; j++) acc[i][j] = 0.f;

    const int lr = tid >> 1;             // 0..127
    const int lc = (tid & 1) * 4;        // 0 or 4
    const bool arow_ok = (bm + lr) < M;
    const float* Aptr = A + (size_t)(bm + lr) * K + lc;
    const float* Bptr = B + (size_t)(bn + lr) * K + lc;

    for (int k0 = 0; k0 < K; k0 += 8) {
        float4 av = arow_ok ? *(const float4*)(Aptr + k0) : make_float4(0.f, 0.f, 0.f, 0.f);
        float4 bv = *(const float4*)(Bptr + k0);
        As[lc + 0][lr] = av.x; As[lc + 1][lr] = av.y; As[lc + 2][lr] = av.z; As[lc + 3][lr] = av.w;
        Bs[lc + 0][lr] = bv.x; Bs[lc + 1][lr] = bv.y; Bs[lc + 2][lr] = bv.z; Bs[lc + 3][lr] = bv.w;
        __syncthreads();
#pragma unroll
        for (int kk = 0; kk < 8; kk++) {
            float af[8], bf[8];
#pragma unroll
            for (int i = 0; i < 8; i++) af[i] = As[kk][ty * 8 + i];
#pragma unroll
            for (int j = 0; j < 8; j++) bf[j] = Bs[kk][tx * 8 + j];
#pragma unroll
            for (int i = 0; i < 8; i++)
#pragma unroll
                for (int j = 0; j < 8; j++) acc[i][j] += af[i] * bf[j];
        }
        __syncthreads();
    }

#pragma unroll
    for (int i = 0; i < 8; i++) {
        int row = bm + ty * 8 + i;
        if (row < M) {
            float* Crow = C + (size_t)row * N + bn + tx * 8;
#pragma unroll
            for (int j = 0; j < 8; j++) {
                float v = acc[i][j];
                if (bias) v += bias[bn + tx * 8 + j];
                Crow[j] = v;
            }
        }
    }
}

// ---------------------------------------------------------------------------
// Elementwise stages
// ---------------------------------------------------------------------------
__global__ void leaf_epilogue() {
    int idx = blockIdx.x * blockDim.x + threadIdx.x;
    if (idx >= NLEAF * HID) return;
    int n = idx >> 9, h = idx & 511;
    const float* g = g_G + (size_t)n * 1536;
    float i = sigf(g[h]);
    float o = sigf(g[512 + h]);
    float u = tanhf(g[1024 + h]);
    float c = i * u;
    int gi = (4369 + n) * HID + h;
    g_C[gi] = c;
    g_H[gi] = o * tanhf(c);
}

// XH[r][0:512] = x[off_d + r], XH[r][512+c] = sum_k H[child(r,k)][c]
__global__ void concat_xh(const float* __restrict__ x, int off_d, int off_c, int n) {
    int idx = blockIdx.x * blockDim.x + threadIdx.x;
    if (idx >= n * 1024) return;
    int r = idx >> 10, c = idx & 1023;
    float v;
    if (c < 512) {
        v = x[(size_t)(off_d + r) * IN_DIM + c];
    } else {
        int hc = c - 512;
        int base = (off_c + r * 16) * HID + hc;
        float s = 0.f;
#pragma unroll
        for (int k = 0; k < 16; k++) s += g_H[base + k * HID];
        v = s;
    }
    g_XH[idx] = v;
}

__global__ void node_epilogue(int off_d, int off_c, int n) {
    int idx = blockIdx.x * blockDim.x + threadIdx.x;
    if (idx >= n * HID) return;
    int r = idx >> 9, h = idx & 511;
    const float* g = g_G + (size_t)r * 2048;
    float i  = sigf(g[h]);
    float o  = sigf(g[512 + h]);
    float u  = tanhf(g[1024 + h]);
    float fx = g[1536 + h];                 // includes b_f
    float acc = i * u;
    int cb = (off_c + r * 16) * HID + h;
#pragma unroll
    for (int k = 0; k < 16; k++) {
        float f = sigf(fx + g_FH[cb + k * HID]);
        acc += f * g_C[cb + k * HID];
    }
    int gi = (off_d + r) * HID + h;
    g_C[gi] = acc;
    g_H[gi] = o * tanhf(acc);
}

__global__ void writeout(float* __restrict__ out) {
    int idx = blockIdx.x * blockDim.x + threadIdx.x;
    if (idx < 512)       out[idx] = g_H[idx];
    else if (idx < 1024) out[idx] = g_C[idx - 512];
}

// ---------------------------------------------------------------------------
// Launch
// ---------------------------------------------------------------------------
static void launch_gemm(const float* A, const float* B, float* C,
                        const float* bias, int M, int N, int K) {
    dim3 grid(N / 128, (M + 127) / 128);
    sgemm<<<grid, 256>>>(A, B, C, bias, M, N, K);
}

extern "C" void kernel_launch(void* const* d_in, const int* in_sizes, int n_in,
                              void* d_out, int out_size) {
    const float* x    = (const float*)d_in[0];
    const float* wi_w = (const float*)d_in[1];
    const float* wi_b = (const float*)d_in[2];
    const float* wf_w = (const float*)d_in[3];
    const float* wf_b = (const float*)d_in[4];
    const float* wo_w = (const float*)d_in[5];
    const float* wo_b = (const float*)d_in[6];
    const float* wu_w = (const float*)d_in[7];
    const float* wu_b = (const float*)d_in[8];
    float* out = (float*)d_out;

    float *pC, *pH, *pFH, *pG, *pXH, *pWl, *pbl, *pWn, *pbn, *pWfh;
    cudaGetSymbolAddress((void**)&pC,   g_C);
    cudaGetSymbolAddress((void**)&pH,   g_H);
    cudaGetSymbolAddress((void**)&pFH,  g_FH);
    cudaGetSymbolAddress((void**)&pG,   g_G);
    cudaGetSymbolAddress((void**)&pXH,  g_XH);
    cudaGetSymbolAddress((void**)&pWl,  g_Wleaf);
    cudaGetSymbolAddress((void**)&pbl,  g_bleaf);
    cudaGetSymbolAddress((void**)&pWn,  g_Wnode);
    cudaGetSymbolAddress((void**)&pbn,  g_bnode);
    cudaGetSymbolAddress((void**)&pWfh, g_Wfh);
    (void)pH;

    static const int offs[6]  = {0, 1, 17, 273, 4369, 69905};
    static const int sizes[5] = {1, 16, 256, 4096, 65536};

    // 1) pack weights
    pack_weights<<<(2048 * 1024 + 255) / 256, 256>>>(wi_w, wi_b, wf_w, wf_b,
                                                     wo_w, wo_b, wu_w, wu_b);

    // 2) leaves
    launch_gemm(x + (size_t)offs[4] * IN_DIM, pWl, pG, pbl, NLEAF, 1536, 512);
    leaf_epilogue<<<(NLEAF * HID) / 256, 256>>>();
    launch_gemm(pC + (size_t)offs[4] * HID, pWfh, pFH + (size_t)offs[4] * HID,
                nullptr, NLEAF, 512, 512);

    // 3) internal levels, bottom-up
    for (int d = 3; d >= 0; d--) {
        int n = sizes[d];
        concat_xh<<<(n * 1024 + 255) / 256, 256>>>(x, offs[d], offs[d + 1], n);
        launch_gemm(pXH, pWn, pG, pbn, n, 2048, 1024);
        node_epilogue<<<(n * HID + 255) / 256, 256>>>(offs[d], offs[d + 1], n);
        if (d > 0)
            launch_gemm(pC + (size_t)offs[d] * HID, pWfh,
                        pFH + (size_t)offs[d] * HID, nullptr, n, 512, 512);
    }

    // 4) output: H[0] then C[0]
    writeout<<<4, 256>>>(out);
}

// round 3
// speedup vs baseline: 2.2402x; 2.2402x over previous
#include <cuda_runtime.h>
#include <cuda_bf16.h>
#include <math.h>
#include <stdint.h>

// ---------------------------------------------------------------------------
// CSTreeLSTM on GB300 (base-PTX path): split-bf16 GEMM on mma.sync HMMA.
// C = (Ah+Al)(Bh+Bl)^T ~= AhBh + AhBl + AlBh  (AlBl dropped, ~2^-18 rel).
// Tree: 16-ary, depth 4, IN=HID=512. Levels 1,16,256,4096,65536
// (offsets 0,1,17,273,4369; total 69905).
// ---------------------------------------------------------------------------

#define IN_DIM 512
#define HID    512
#define NLEAF  65536
#define NTOT   69905

typedef __nv_bfloat16 bf16;

// ------------------------------ device scratch ------------------------------
__device__ __align__(128) float g_C [NTOT * HID];
__device__ __align__(128) float g_H [NTOT * HID];
__device__ __align__(128) float g_FH[NTOT * HID];
__device__ __align__(128) float g_G [NLEAF * 1536];

__device__ __align__(128) bf16 g_Xh [NLEAF * IN_DIM];
__device__ __align__(128) bf16 g_Xl [NLEAF * IN_DIM];
__device__ __align__(128) bf16 g_Ch [NTOT * HID];
__device__ __align__(128) bf16 g_Cl [NTOT * HID];
__device__ __align__(128) bf16 g_XHh[4096 * 1024];
__device__ __align__(128) bf16 g_XHl[4096 * 1024];

__device__ __align__(128) bf16 g_Wnh[2048 * 1024];
__device__ __align__(128) bf16 g_Wnl[2048 * 1024];
__device__ __align__(128) bf16 g_Wlh[1536 * 512];
__device__ __align__(128) bf16 g_Wll[1536 * 512];
__device__ __align__(128) bf16 g_Wfhh[512 * 512];
__device__ __align__(128) bf16 g_Wfhl[512 * 512];
__device__ float g_bleaf[1536];
__device__ float g_bnode[2048];

__device__ __forceinline__ float sigf(float x) { return 1.f / (1.f + expf(-x)); }

__device__ __forceinline__ void split1(float v, bf16& h, bf16& l) {
    h = __float2bfloat16(v);
    l = __float2bfloat16(v - __bfloat162float(h));
}

// ------------------------------ PTX helpers ---------------------------------
__device__ __forceinline__ uint32_t smem_u32(const void* p) {
    uint32_t a;
    asm("{ .reg .u64 t; cvta.to.shared.u64 t, %1; cvt.u32.u64 %0, t; }" : "=r"(a) : "l"(p));
    return a;
}

__device__ __forceinline__ void cp16(uint32_t dst, const void* src) {
    asm volatile("cp.async.cg.shared.global [%0], [%1], 16;" :: "r"(dst), "l"(src));
}
#define CP_COMMIT() asm volatile("cp.async.commit_group;" ::: "memory")

__device__ __forceinline__ void ldsm4(uint32_t* r, uint32_t addr) {
    asm volatile("ldmatrix.sync.aligned.m8n8.x4.shared.b16 {%0,%1,%2,%3}, [%4];"
                 : "=r"(r[0]), "=r"(r[1]), "=r"(r[2]), "=r"(r[3]) : "r"(addr));
}
__device__ __forceinline__ void ldsm2(uint32_t* r, uint32_t addr) {
    asm volatile("ldmatrix.sync.aligned.m8n8.x2.shared.b16 {%0,%1}, [%2];"
                 : "=r"(r[0]), "=r"(r[1]) : "r"(addr));
}
__device__ __forceinline__ void mma16816(float* d, const uint32_t* a, const uint32_t* b) {
    asm volatile(
        "mma.sync.aligned.m16n8k16.row.col.f32.bf16.bf16.f32 "
        "{%0,%1,%2,%3}, {%4,%5,%6,%7}, {%8,%9}, {%0,%1,%2,%3};"
        : "+f"(d[0]), "+f"(d[1]), "+f"(d[2]), "+f"(d[3])
        : "r"(a[0]), "r"(a[1]), "r"(a[2]), "r"(a[3]), "r"(b[0]), "r"(b[1]));
}

// ---------------------------------------------------------------------------
// Split-bf16 GEMM: C[M,N] = (Ah+Al)[M,K] * (Bh+Bl)[N,K]^T (+ bias[N])
// CTA tile 128x128, BK=32, 8 warps (warp tile 32x64), 3-stage cp.async.
// SMEM tiles: 128 rows x 32 bf16, row pitch 80B (conflict-free ldmatrix).
// N % 128 == 0, K % 32 == 0; M guarded (loads clamped, stores masked).
// ---------------------------------------------------------------------------
#define TPITCH 80                         // bytes per smem tile row
#define TILE_B (128 * TPITCH)             // 10240 bytes per tile
#define STAGE_B (4 * TILE_B)              // Ah, Al, Bh, Bl
#define NSTAGE 3
#define GSMEM (NSTAGE * STAGE_B + 128)

__global__ __launch_bounds__(256)
void gemm_split(const bf16* __restrict__ Ah, const bf16* __restrict__ Al,
                const bf16* __restrict__ Bh, const bf16* __restrict__ Bl,
                float* __restrict__ C, const float* __restrict__ bias,
                int M, int N, int K) {
    extern __shared__ char smem_raw[];
    const uint32_t sbase = (smem_u32(smem_raw) + 127) & ~127u;

    const int tid  = threadIdx.x;
    const int lane = tid & 31;
    const int wid  = tid >> 5;
    const int wm   = wid >> 1;              // 0..3 (M)
    const int wn   = wid & 1;               // 0..1 (N)
    const int bm   = blockIdx.y * 128;
    const int bn   = blockIdx.x * 128;
    const int NC   = K >> 5;

    // cp.async thread mapping: 512 16B-chunks per tile, 2 per thread
    const int ldr0 = tid >> 2;              // row for iter 0 (0..63)
    const int ldc  = (tid & 3) * 16;        // 16B chunk in row
    const int gk   = (tid & 3) * 8;         // k element offset of chunk

    // ldmatrix address components
    const int ag = lane >> 3, ai = lane & 7;
    const int a_row = ai + (ag & 1) * 8;    // + m0
    const int a_kb  = (ag >> 1) * 16;       // + 2*k0
    const int b_row = lane & 7;             // + n0
    const int b_kb  = ((lane >> 3) & 1) * 16;

    float acc[2][8][4];
#pragma unroll
    for (int mt = 0; mt < 2; mt++)
#pragma unroll
        for (int nt = 0; nt < 8; nt++)
#pragma unroll
            for (int j = 0; j < 4; j++) acc[mt][nt][j] = 0.f;

    // ---- load one K-chunk into stage s ----
    auto load_chunk = [&](int c, int s) {
        const uint32_t sb = sbase + s * STAGE_B;
        const int k0 = c << 5;
#pragma unroll
        for (int it = 0; it < 2; ++it) {
            int row = ldr0 + it * 64;
            int ar = bm + row; if (ar > M - 1) ar = M - 1;
            size_t aoff = (size_t)ar * K + k0 + gk;
            size_t boff = (size_t)(bn + row) * K + k0 + gk;
            uint32_t so = row * TPITCH + ldc;
            cp16(sb + so,              Ah + aoff);
            cp16(sb + TILE_B + so,     Al + aoff);
            cp16(sb + 2 * TILE_B + so, Bh + boff);
            cp16(sb + 3 * TILE_B + so, Bl + boff);
        }
        CP_COMMIT();
    };

    load_chunk(0, 0);
    if (NC > 1) load_chunk(1, 1);

    for (int c = 0; c < NC; ++c) {
        if (c + 2 < NC) load_chunk(c + 2, (c + 2) % NSTAGE);

        if (c + 2 < NC)      asm volatile("cp.async.wait_group 2;" ::: "memory");
        else if (c + 1 < NC) asm volatile("cp.async.wait_group 1;" ::: "memory");
        else                 asm volatile("cp.async.wait_group 0;" ::: "memory");
        __syncthreads();

        const uint32_t sb  = sbase + (c % NSTAGE) * STAGE_B;
        const uint32_t tAh = sb,            tAl = sb + TILE_B;
        const uint32_t tBh = sb + 2*TILE_B, tBl = sb + 3*TILE_B;

#pragma unroll
        for (int ks = 0; ks < 2; ++ks) {
            const int kb = ks * 32;    // byte offset of k16 step
            uint32_t ah[2][4], al[2][4], bh[8][2], bl[8][2];
#pragma unroll
            for (int mt = 0; mt < 2; ++mt) {
                uint32_t ro = (wm * 32 + mt * 16 + a_row) * TPITCH + a_kb + kb;
                ldsm4(ah[mt], tAh + ro);
                ldsm4(al[mt], tAl + ro);
            }
#pragma unroll
            for (int nt = 0; nt < 8; ++nt) {
                uint32_t ro = (wn * 64 + nt * 8 + b_row) * TPITCH + b_kb + kb;
                ldsm2(bh[nt], tBh + ro);
                ldsm2(bl[nt], tBl + ro);
            }
#pragma unroll
            for (int mt = 0; mt < 2; ++mt)
#pragma unroll
                for (int nt = 0; nt < 8; ++nt) {
                    mma16816(acc[mt][nt], ah[mt], bh[nt]);
                    mma16816(acc[mt][nt], ah[mt], bl[nt]);
                    mma16816(acc[mt][nt], al[mt], bh[nt]);
                }
        }
        __syncthreads();
    }

    // ---- epilogue: direct global stores (float2 per fragment row) ----
    const int r0 = lane >> 2;
    const int q2 = (lane & 3) * 2;
#pragma unroll
    for (int mt = 0; mt < 2; ++mt) {
        int row = bm + wm * 32 + mt * 16 + r0;
#pragma unroll
        for (int nt = 0; nt < 8; ++nt) {
            int col = bn + wn * 64 + nt * 8 + q2;
            float bx = 0.f, by = 0.f;
            if (bias) { bx = bias[col]; by = bias[col + 1]; }
            if (row < M) {
                float2 v = make_float2(acc[mt][nt][0] + bx, acc[mt][nt][1] + by);
                *(float2*)(C + (size_t)row * N + col) = v;
            }
            if (row + 8 < M) {
                float2 v = make_float2(acc[mt][nt][2] + bx, acc[mt][nt][3] + by);
                *(float2*)(C + (size_t)(row + 8) * N + col) = v;
            }
        }
    }
}

// ---------------------------------------------------------------------------
// Weight packing (fp32 -> split bf16) + biases
// ---------------------------------------------------------------------------
__global__ void pack_weights(const float* __restrict__ wi_w, const float* __restrict__ wi_b,
                             const float* __restrict__ wf_w, const float* __restrict__ wf_b,
                             const float* __restrict__ wo_w, const float* __restrict__ wo_b,
                             const float* __restrict__ wu_w, const float* __restrict__ wu_b) {
    int idx = blockIdx.x * blockDim.x + threadIdx.x;

    if (idx < 2048 * 1024) {                     // Wnode [2048][1024]
        int r = idx >> 10, k = idx & 1023;
        float v;
        if      (r <  512) v = wi_w[r * 1024 + k];
        else if (r < 1024) v = wo_w[(r -  512) * 1024 + k];
        else if (r < 1536) v = wu_w[(r - 1024) * 1024 + k];
        else               v = (k < 512) ? wf_w[(r - 1536) * 1024 + k] : 0.f;
        split1(v, g_Wnh[idx], g_Wnl[idx]);
    }
    if (idx < 1536 * 512) {                      // Wleaf [1536][512]
        int r = idx >> 9, k = idx & 511;
        float v;
        if      (r <  512) v = wi_w[r * 1024 + k];
        else if (r < 1024) v = wo_w[(r -  512) * 1024 + k];
        else               v = wu_w[(r - 1024) * 1024 + k];
        split1(v, g_Wlh[idx], g_Wll[idx]);
    }
    if (idx < 512 * 512) {                       // Wfh [512][512]
        int r = idx >> 9, k = idx & 511;
        split1(wf_w[r * 1024 + 512 + k], g_Wfhh[idx], g_Wfhl[idx]);
    }
    if (idx < 1536)
        g_bleaf[idx] = (idx < 512) ? wi_b[idx] : (idx < 1024) ? wo_b[idx - 512] : wu_b[idx - 1024];
    if (idx < 2048)
        g_bnode[idx] = (idx <  512) ? wi_b[idx]
                     : (idx < 1024) ? wo_b[idx -  512]
                     : (idx < 1536) ? wu_b[idx - 1024] : wf_b[idx - 1536];
}

// fp32 -> split bf16, 4 elems/thread
__global__ void split4(const float* __restrict__ src, bf16* __restrict__ h,
                       bf16* __restrict__ l, int n4) {
    int i = blockIdx.x * blockDim.x + threadIdx.x;
    if (i >= n4) return;
    float4 v = ((const float4*)src)[i];
    bf16 hh[4], ll[4];
    split1(v.x, hh[0], ll[0]); split1(v.y, hh[1], ll[1]);
    split1(v.z, hh[2], ll[2]); split1(v.w, hh[3], ll[3]);
    ((uint2*)h)[i] = *(uint2*)hh;
    ((uint2*)l)[i] = *(uint2*)ll;
}

// ---------------------------------------------------------------------------
// Elementwise stages
// ---------------------------------------------------------------------------
__global__ void leaf_epilogue() {
    int idx = blockIdx.x * blockDim.x + threadIdx.x;
    if (idx >= NLEAF * HID) return;
    int n = idx >> 9, h = idx & 511;
    const float* g = g_G + (size_t)n * 1536;
    float i = sigf(g[h]);
    float o = sigf(g[512 + h]);
    float u = tanhf(g[1024 + h]);
    float c = i * u;
    size_t gi = (size_t)(4369 + n) * HID + h;
    g_C[gi] = c;
    g_H[gi] = o * tanhf(c);
    split1(c, g_Ch[gi], g_Cl[gi]);
}

// XH[r][0:512] = x[off_d + r]; XH[r][512+c] = sum_k H[child]; split bf16 out
__global__ void concat_xh_split(const float* __restrict__ x, int off_d, int off_c, int n) {
    int idx = blockIdx.x * blockDim.x + threadIdx.x;
    if (idx >= n * 1024) return;
    int r = idx >> 10, c = idx & 1023;
    float v;
    if (c < 512) {
        v = x[(size_t)(off_d + r) * IN_DIM + c];
    } else {
        int hc = c - 512;
        size_t base = (size_t)(off_c + r * 16) * HID + hc;
        float s = 0.f;
#pragma unroll
        for (int k = 0; k < 16; k++) s += g_H[base + k * HID];
        v = s;
    }
    split1(v, g_XHh[idx], g_XHl[idx]);
}

__global__ void node_epilogue(int off_d, int off_c, int n) {
    int idx = blockIdx.x * blockDim.x + threadIdx.x;
    if (idx >= n * HID) return;
    int r = idx >> 9, h = idx & 511;
    const float* g = g_G + (size_t)r * 2048;
    float i  = sigf(g[h]);
    float o  = sigf(g[512 + h]);
    float u  = tanhf(g[1024 + h]);
    float fx = g[1536 + h];
    float acc = i * u;
    size_t cb = (size_t)(off_c + r * 16) * HID + h;
#pragma unroll
    for (int k = 0; k < 16; k++) {
        float f = sigf(fx + g_FH[cb + k * HID]);
        acc += f * g_C[cb + k * HID];
    }
    size_t gi = (size_t)(off_d + r) * HID + h;
    g_C[gi] = acc;
    g_H[gi] = o * tanhf(acc);
    split1(acc, g_Ch[gi], g_Cl[gi]);
}

__global__ void writeout(float* __restrict__ out) {
    int idx = blockIdx.x * blockDim.x + threadIdx.x;
    if (idx < 512)       out[idx] = g_H[idx];
    else if (idx < 1024) out[idx] = g_C[idx - 512];
}

// ---------------------------------------------------------------------------
// Launch
// ---------------------------------------------------------------------------
static void launch_gemm(const bf16* Ah, const bf16* Al, const bf16* Bh, const bf16* Bl,
                        float* C, const float* bias, int M, int N, int K) {
    dim3 grid(N / 128, (M + 127) / 128);
    gemm_split<<<grid, 256, GSMEM>>>(Ah, Al, Bh, Bl, C, bias, M, N, K);
}

extern "C" void kernel_launch(void* const* d_in, const int* in_sizes, int n_in,
                              void* d_out, int out_size) {
    const float* x    = (const float*)d_in[0];
    const float* wi_w = (const float*)d_in[1];
    const float* wi_b = (const float*)d_in[2];
    const float* wf_w = (const float*)d_in[3];
    const float* wf_b = (const float*)d_in[4];
    const float* wo_w = (const float*)d_in[5];
    const float* wo_b = (const float*)d_in[6];
    const float* wu_w = (const float*)d_in[7];
    const float* wu_b = (const float*)d_in[8];
    float* out = (float*)d_out;

    cudaFuncSetAttribute(gemm_split, cudaFuncAttributeMaxDynamicSharedMemorySize, GSMEM);

    float *pC, *pFH, *pG, *pbl, *pbn;
    bf16 *pXh, *pXl, *pCh, *pCl, *pXHh, *pXHl, *pWnh, *pWnl, *pWlh, *pWll, *pWfhh, *pWfhl;
    cudaGetSymbolAddress((void**)&pC,    g_C);
    cudaGetSymbolAddress((void**)&pFH,   g_FH);
    cudaGetSymbolAddress((void**)&pG,    g_G);
    cudaGetSymbolAddress((void**)&pbl,   g_bleaf);
    cudaGetSymbolAddress((void**)&pbn,   g_bnode);
    cudaGetSymbolAddress((void**)&pXh,   g_Xh);
    cudaGetSymbolAddress((void**)&pXl,   g_Xl);
    cudaGetSymbolAddress((void**)&pCh,   g_Ch);
    cudaGetSymbolAddress((void**)&pCl,   g_Cl);
    cudaGetSymbolAddress((void**)&pXHh,  g_XHh);
    cudaGetSymbolAddress((void**)&pXHl,  g_XHl);
    cudaGetSymbolAddress((void**)&pWnh,  g_Wnh);
    cudaGetSymbolAddress((void**)&pWnl,  g_Wnl);
    cudaGetSymbolAddress((void**)&pWlh,  g_Wlh);
    cudaGetSymbolAddress((void**)&pWll,  g_Wll);
    cudaGetSymbolAddress((void**)&pWfhh, g_Wfhh);
    cudaGetSymbolAddress((void**)&pWfhl, g_Wfhl);

    static const int offs[6]  = {0, 1, 17, 273, 4369, 69905};
    static const int sizes[5] = {1, 16, 256, 4096, 65536};

    // 1) weights -> split bf16
    pack_weights<<<(2048 * 1024 + 255) / 256, 256>>>(wi_w, wi_b, wf_w, wf_b,
                                                     wo_w, wo_b, wu_w, wu_b);
    // 2) leaf x -> split bf16
    split4<<<(NLEAF * IN_DIM / 4 + 255) / 256, 256>>>(x + (size_t)offs[4] * IN_DIM,
                                                      pXh, pXl, NLEAF * IN_DIM / 4);
    // 3) leaf gates + epilogue + FH
    launch_gemm(pXh, pXl, pWlh, pWll, pG, pbl, NLEAF, 1536, 512);
    leaf_epilogue<<<(NLEAF * HID) / 256, 256>>>();
    launch_gemm(pCh + (size_t)offs[4] * HID, pCl + (size_t)offs[4] * HID,
                pWfhh, pWfhl, pFH + (size_t)offs[4] * HID, nullptr, NLEAF, 512, 512);

    // 4) internal levels, bottom-up
    for (int d = 3; d >= 0; d--) {
        int n = sizes[d];
        concat_xh_split<<<(n * 1024 + 255) / 256, 256>>>(x, offs[d], offs[d + 1], n);
        launch_gemm(pXHh, pXHl, pWnh, pWnl, pG, pbn, n, 2048, 1024);
        node_epilogue<<<(n * HID + 255) / 256, 256>>>(offs[d], offs[d + 1], n);
        if (d > 0)
            launch_gemm(pCh + (size_t)offs[d] * HID, pCl + (size_t)offs[d] * HID,
                        pWfhh, pWfhl, pFH + (size_t)offs[d] * HID, nullptr, n, 512, 512);
    }

    // 5) output: H[0] then C[0]
    writeout<<<4, 256>>>(out);
}

// round 4
// speedup vs baseline: 2.6147x; 1.1671x over previous
#include <cuda_runtime.h>
#include <cuda_bf16.h>
#include <math.h>
#include <stdint.h>

// ---------------------------------------------------------------------------
// CSTreeLSTM on GB300: split-bf16 HMMA GEMMs, fused leaf gate kernel.
// C = (Ah+Al)(Bh+Bl)^T ~= AhBh + AhBl + AlBh.
// Tree: 16-ary, depth 4, IN=HID=512. Levels 1,16,256,4096,65536
// (offsets 0,1,17,273,4369; total 69905).
// ---------------------------------------------------------------------------

#define IN_DIM 512
#define HID    512
#define NLEAF  65536
#define NTOT   69905

typedef __nv_bfloat16 bf16;

// ------------------------------ device scratch ------------------------------
__device__ __align__(128) float g_C [NTOT * HID];
__device__ __align__(128) float g_H [NTOT * HID];
__device__ __align__(128) float g_FH[NTOT * HID];
__device__ __align__(128) float g_G [4096 * 2048];   // node-level gates only

__device__ __align__(128) bf16 g_Xh [NLEAF * IN_DIM];
__device__ __align__(128) bf16 g_Xl [NLEAF * IN_DIM];
__device__ __align__(128) bf16 g_Ch [NTOT * HID];
__device__ __align__(128) bf16 g_Cl [NTOT * HID];
__device__ __align__(128) bf16 g_XHh[4096 * 1024];
__device__ __align__(128) bf16 g_XHl[4096 * 1024];

__device__ __align__(128) bf16 g_Wnh[2048 * 1024];
__device__ __align__(128) bf16 g_Wnl[2048 * 1024];
__device__ __align__(128) bf16 g_Wlh[1536 * 512];
__device__ __align__(128) bf16 g_Wll[1536 * 512];
__device__ __align__(128) bf16 g_Wfhh[512 * 512];
__device__ __align__(128) bf16 g_Wfhl[512 * 512];
__device__ float g_bleaf[1536];
__device__ float g_bnode[2048];

__device__ __forceinline__ float sigf(float x) { return 1.f / (1.f + expf(-x)); }

__device__ __forceinline__ void split1(float v, bf16& h, bf16& l) {
    h = __float2bfloat16(v);
    l = __float2bfloat16(v - __bfloat162float(h));
}

// ------------------------------ PTX helpers ---------------------------------
__device__ __forceinline__ uint32_t smem_u32(const void* p) {
    uint32_t a;
    asm("{ .reg .u64 t; cvta.to.shared.u64 t, %1; cvt.u32.u64 %0, t; }" : "=r"(a) : "l"(p));
    return a;
}

__device__ __forceinline__ void cp16(uint32_t dst, const void* src) {
    asm volatile("cp.async.cg.shared.global [%0], [%1], 16;" :: "r"(dst), "l"(src));
}
#define CP_COMMIT() asm volatile("cp.async.commit_group;" ::: "memory")

__device__ __forceinline__ void ldsm4(uint32_t* r, uint32_t addr) {
    asm volatile("ldmatrix.sync.aligned.m8n8.x4.shared.b16 {%0,%1,%2,%3}, [%4];"
                 : "=r"(r[0]), "=r"(r[1]), "=r"(r[2]), "=r"(r[3]) : "r"(addr));
}
__device__ __forceinline__ void ldsm2(uint32_t* r, uint32_t addr) {
    asm volatile("ldmatrix.sync.aligned.m8n8.x2.shared.b16 {%0,%1}, [%2];"
                 : "=r"(r[0]), "=r"(r[1]) : "r"(addr));
}
__device__ __forceinline__ void mma16816(float* d, const uint32_t* a, const uint32_t* b) {
    asm volatile(
        "mma.sync.aligned.m16n8k16.row.col.f32.bf16.bf16.f32 "
        "{%0,%1,%2,%3}, {%4,%5,%6,%7}, {%8,%9}, {%0,%1,%2,%3};"
        : "+f"(d[0]), "+f"(d[1]), "+f"(d[2]), "+f"(d[3])
        : "r"(a[0]), "r"(a[1]), "r"(a[2]), "r"(a[3]), "r"(b[0]), "r"(b[1]));
}

// ---------------------------------------------------------------------------
// Fused leaf kernel: for each (node row, hidden col) computes all three gate
// pre-activations via split-bf16 HMMA, applies nonlinearities, writes
// C,H (fp32) and Ch,Cl (bf16) directly. No g_G roundtrip.
// CTA tile: 128 (M) x 64 (h), 8 warps, warp tile 32x32, BK=32, 3 stages.
// M = 65536 (multiple of 128): no guards. K = 512.
// ---------------------------------------------------------------------------
#define LF_PITCH 80
#define LF_AT (128 * LF_PITCH)            // 10240
#define LF_BT (64 * LF_PITCH)             // 5120
#define LF_STAGE (2 * LF_AT + 6 * LF_BT)  // 51200
#define LF_SMEM (3 * LF_STAGE + 128)

__global__ __launch_bounds__(256)
void leaf_fused(const bf16* __restrict__ Ah, const bf16* __restrict__ Al) {
    extern __shared__ char smem_raw[];
    const uint32_t sbase = (smem_u32(smem_raw) + 127) & ~127u;

    const int tid  = threadIdx.x;
    const int lane = tid & 31;
    const int wid  = tid >> 5;
    const int wm   = wid >> 1;             // 0..3
    const int wn   = wid & 1;              // 0..1
    const int bm   = blockIdx.y * 128;
    const int bh   = blockIdx.x * 64;
    const int K    = 512;
    const int NC   = 16;

    const int ag = lane >> 3, ai = lane & 7;
    const int a_row = ai + (ag & 1) * 8;
    const int a_kb  = (ag >> 1) * 16;
    const int b_row = lane & 7;
    const int b_kb  = ((lane >> 3) & 1) * 16;

    float acc[3][2][4][4];
#pragma unroll
    for (int g = 0; g < 3; g++)
#pragma unroll
        for (int mt = 0; mt < 2; mt++)
#pragma unroll
            for (int nt = 0; nt < 4; nt++)
#pragma unroll
                for (int j = 0; j < 4; j++) acc[g][mt][nt][j] = 0.f;

    auto load_chunk = [&](int c, int s) {
        const uint32_t sb = sbase + s * LF_STAGE;
        const int k0 = c << 5;
#pragma unroll
        for (int i = 0; i < 2; ++i) {
            int idx = tid + i * 256;
            int row = idx >> 2, cb = idx & 3;
            size_t aoff = (size_t)(bm + row) * K + k0 + cb * 8;
            uint32_t so = row * LF_PITCH + cb * 16;
            cp16(sb + so,         Ah + aoff);
            cp16(sb + LF_AT + so, Al + aoff);
        }
        {
            int row = tid >> 2, cb = tid & 3;
            uint32_t so = row * LF_PITCH + cb * 16;
#pragma unroll
            for (int g = 0; g < 3; ++g) {
                size_t woff = (size_t)(g * 512 + bh + row) * 512 + k0 + cb * 8;
                uint32_t base = sb + 2 * LF_AT + g * 2 * LF_BT;
                cp16(base + so,         g_Wlh + woff);
                cp16(base + LF_BT + so, g_Wll + woff);
            }
        }
        CP_COMMIT();
    };

    load_chunk(0, 0);
    load_chunk(1, 1);

    for (int c = 0; c < NC; ++c) {
        if (c + 2 < NC) load_chunk(c + 2, (c + 2) % 3);

        if (c + 2 < NC)      asm volatile("cp.async.wait_group 2;" ::: "memory");
        else if (c + 1 < NC) asm volatile("cp.async.wait_group 1;" ::: "memory");
        else                 asm volatile("cp.async.wait_group 0;" ::: "memory");
        __syncthreads();

        const uint32_t sb = sbase + (c % 3) * LF_STAGE;

#pragma unroll
        for (int ks = 0; ks < 2; ++ks) {
            const int kb = ks * 32;
            uint32_t ah[2][4], al[2][4];
#pragma unroll
            for (int mt = 0; mt < 2; ++mt) {
                uint32_t ro = (wm * 32 + mt * 16 + a_row) * LF_PITCH + a_kb + kb;
                ldsm4(ah[mt], sb + ro);
                ldsm4(al[mt], sb + LF_AT + ro);
            }
#pragma unroll
            for (int g = 0; g < 3; ++g) {
                const uint32_t base = sb + 2 * LF_AT + g * 2 * LF_BT;
                uint32_t bhf[4][2], blf[4][2];
#pragma unroll
                for (int nt = 0; nt < 4; ++nt) {
                    uint32_t ro = (wn * 32 + nt * 8 + b_row) * LF_PITCH + b_kb + kb;
                    ldsm2(bhf[nt], base + ro);
                    ldsm2(blf[nt], base + LF_BT + ro);
                }
#pragma unroll
                for (int mt = 0; mt < 2; ++mt)
#pragma unroll
                    for (int nt = 0; nt < 4; ++nt) {
                        mma16816(acc[g][mt][nt], ah[mt], bhf[nt]);
                        mma16816(acc[g][mt][nt], ah[mt], blf[nt]);
                        mma16816(acc[g][mt][nt], al[mt], bhf[nt]);
                    }
            }
        }
        __syncthreads();
    }

    // epilogue: gates -> C,H,Ch,Cl
    const int r0 = lane >> 2;
    const int q2 = (lane & 3) * 2;
#pragma unroll
    for (int mt = 0; mt < 2; ++mt) {
#pragma unroll
        for (int nt = 0; nt < 4; ++nt) {
            int col = bh + wn * 32 + nt * 8 + q2;
            float bi0 = g_bleaf[col],        bi1 = g_bleaf[col + 1];
            float bo0 = g_bleaf[512 + col],  bo1 = g_bleaf[512 + col + 1];
            float bu0 = g_bleaf[1024 + col], bu1 = g_bleaf[1024 + col + 1];
#pragma unroll
            for (int hf = 0; hf < 2; ++hf) {
                int row = bm + wm * 32 + mt * 16 + r0 + hf * 8;
                float i0 = sigf(acc[0][mt][nt][hf * 2 + 0] + bi0);
                float i1 = sigf(acc[0][mt][nt][hf * 2 + 1] + bi1);
                float o0 = sigf(acc[1][mt][nt][hf * 2 + 0] + bo0);
                float o1 = sigf(acc[1][mt][nt][hf * 2 + 1] + bo1);
                float u0 = tanhf(acc[2][mt][nt][hf * 2 + 0] + bu0);
                float u1 = tanhf(acc[2][mt][nt][hf * 2 + 1] + bu1);
                float c0 = i0 * u0, c1 = i1 * u1;
                float h0 = o0 * tanhf(c0), h1 = o1 * tanhf(c1);
                size_t gi = (size_t)(4369 + row) * HID + col;
                *(float2*)(g_C + gi) = make_float2(c0, c1);
                *(float2*)(g_H + gi) = make_float2(h0, h1);
                bf16 hh0, ll0, hh1, ll1;
                split1(c0, hh0, ll0); split1(c1, hh1, ll1);
                __nv_bfloat162 vh; vh.x = hh0; vh.y = hh1;
                __nv_bfloat162 vl; vl.x = ll0; vl.y = ll1;
                *(__nv_bfloat162*)(g_Ch + gi) = vh;
                *(__nv_bfloat162*)(g_Cl + gi) = vl;
            }
        }
    }
}

// ---------------------------------------------------------------------------
// Split-bf16 GEMM, CTA 128x128 (big shapes). Same as Round 3.
// ---------------------------------------------------------------------------
#define TPITCH 80
#define TILE_B (128 * TPITCH)
#define STAGE_B (4 * TILE_B)
#define GSMEM (3 * STAGE_B + 128)

__global__ __launch_bounds__(256)
void gemm_split(const bf16* __restrict__ Ah, const bf16* __restrict__ Al,
                const bf16* __restrict__ Bh, const bf16* __restrict__ Bl,
                float* __restrict__ C, const float* __restrict__ bias,
                int M, int N, int K) {
    extern __shared__ char smem_raw[];
    const uint32_t sbase = (smem_u32(smem_raw) + 127) & ~127u;

    const int tid  = threadIdx.x;
    const int lane = tid & 31;
    const int wid  = tid >> 5;
    const int wm   = wid >> 1;
    const int wn   = wid & 1;
    const int bm   = blockIdx.y * 128;
    const int bn   = blockIdx.x * 128;
    const int NC   = K >> 5;

    const int ldr0 = tid >> 2;
    const int ldc  = (tid & 3) * 16;
    const int gk   = (tid & 3) * 8;

    const int ag = lane >> 3, ai = lane & 7;
    const int a_row = ai + (ag & 1) * 8;
    const int a_kb  = (ag >> 1) * 16;
    const int b_row = lane & 7;
    const int b_kb  = ((lane >> 3) & 1) * 16;

    float acc[2][8][4];
#pragma unroll
    for (int mt = 0; mt < 2; mt++)
#pragma unroll
        for (int nt = 0; nt < 8; nt++)
#pragma unroll
            for (int j = 0; j < 4; j++) acc[mt][nt][j] = 0.f;

    auto load_chunk = [&](int c, int s) {
        const uint32_t sb = sbase + s * STAGE_B;
        const int k0 = c << 5;
#pragma unroll
        for (int it = 0; it < 2; ++it) {
            int row = ldr0 + it * 64;
            int ar = bm + row; if (ar > M - 1) ar = M - 1;
            size_t aoff = (size_t)ar * K + k0 + gk;
            size_t boff = (size_t)(bn + row) * K + k0 + gk;
            uint32_t so = row * TPITCH + ldc;
            cp16(sb + so,              Ah + aoff);
            cp16(sb + TILE_B + so,     Al + aoff);
            cp16(sb + 2 * TILE_B + so, Bh + boff);
            cp16(sb + 3 * TILE_B + so, Bl + boff);
        }
        CP_COMMIT();
    };

    load_chunk(0, 0);
    if (NC > 1) load_chunk(1, 1);

    for (int c = 0; c < NC; ++c) {
        if (c + 2 < NC) load_chunk(c + 2, (c + 2) % 3);

        if (c + 2 < NC)      asm volatile("cp.async.wait_group 2;" ::: "memory");
        else if (c + 1 < NC) asm volatile("cp.async.wait_group 1;" ::: "memory");
        else                 asm volatile("cp.async.wait_group 0;" ::: "memory");
        __syncthreads();

        const uint32_t sb  = sbase + (c % 3) * STAGE_B;
        const uint32_t tAh = sb,              tAl = sb + TILE_B;
        const uint32_t tBh = sb + 2 * TILE_B, tBl = sb + 3 * TILE_B;

#pragma unroll
        for (int ks = 0; ks < 2; ++ks) {
            const int kb = ks * 32;
            uint32_t ah[2][4], al[2][4], bhf[8][2], blf[8][2];
#pragma unroll
            for (int mt = 0; mt < 2; ++mt) {
                uint32_t ro = (wm * 32 + mt * 16 + a_row) * TPITCH + a_kb + kb;
                ldsm4(ah[mt], tAh + ro);
                ldsm4(al[mt], tAl + ro);
            }
#pragma unroll
            for (int nt = 0; nt < 8; ++nt) {
                uint32_t ro = (wn * 64 + nt * 8 + b_row) * TPITCH + b_kb + kb;
                ldsm2(bhf[nt], tBh + ro);
                ldsm2(blf[nt], tBl + ro);
            }
#pragma unroll
            for (int mt = 0; mt < 2; ++mt)
#pragma unroll
                for (int nt = 0; nt < 8; ++nt) {
                    mma16816(acc[mt][nt], ah[mt], bhf[nt]);
                    mma16816(acc[mt][nt], ah[mt], blf[nt]);
                    mma16816(acc[mt][nt], al[mt], bhf[nt]);
                }
        }
        __syncthreads();
    }

    const int r0 = lane >> 2;
    const int q2 = (lane & 3) * 2;
#pragma unroll
    for (int mt = 0; mt < 2; ++mt) {
        int row = bm + wm * 32 + mt * 16 + r0;
#pragma unroll
        for (int nt = 0; nt < 8; ++nt) {
            int col = bn + wn * 64 + nt * 8 + q2;
            float bx = 0.f, by = 0.f;
            if (bias) { bx = bias[col]; by = bias[col + 1]; }
            if (row < M)
                *(float2*)(C + (size_t)row * N + col) =
                    make_float2(acc[mt][nt][0] + bx, acc[mt][nt][1] + by);
            if (row + 8 < M)
                *(float2*)(C + (size_t)(row + 8) * N + col) =
                    make_float2(acc[mt][nt][2] + bx, acc[mt][nt][3] + by);
        }
    }
}

// ---------------------------------------------------------------------------
// Split-bf16 GEMM, CTA 64x64 (small M tail). 128 threads, 4 warps 32x32.
// ---------------------------------------------------------------------------
#define G64_T (64 * TPITCH)        // 5120
#define G64_STAGE (4 * G64_T)      // 20480
#define G64_SMEM (3 * G64_STAGE + 128)

__global__ __launch_bounds__(128)
void gemm_split64(const bf16* __restrict__ Ah, const bf16* __restrict__ Al,
                  const bf16* __restrict__ Bh, const bf16* __restrict__ Bl,
                  float* __restrict__ C, const float* __restrict__ bias,
                  int M, int N, int K) {
    extern __shared__ char smem_raw[];
    const uint32_t sbase = (smem_u32(smem_raw) + 127) & ~127u;

    const int tid  = threadIdx.x;
    const int lane = tid & 31;
    const int wid  = tid >> 5;
    const int wm   = wid >> 1;          // 0..1
    const int wn   = wid & 1;           // 0..1
    const int bm   = blockIdx.y * 64;
    const int bn   = blockIdx.x * 64;
    const int NC   = K >> 5;

    const int ag = lane >> 3, ai = lane & 7;
    const int a_row = ai + (ag & 1) * 8;
    const int a_kb  = (ag >> 1) * 16;
    const int b_row = lane & 7;
    const int b_kb  = ((lane >> 3) & 1) * 16;

    float acc[2][4][4];
#pragma unroll
    for (int mt = 0; mt < 2; mt++)
#pragma unroll
        for (int nt = 0; nt < 4; nt++)
#pragma unroll
            for (int j = 0; j < 4; j++) acc[mt][nt][j] = 0.f;

    auto load_chunk = [&](int c, int s) {
        const uint32_t sb = sbase + s * G64_STAGE;
        const int k0 = c << 5;
#pragma unroll
        for (int it = 0; it < 2; ++it) {
            int idx = tid + it * 128;
            int row = idx >> 2, cb = idx & 3;
            int ar = bm + row; if (ar > M - 1) ar = M - 1;
            size_t aoff = (size_t)ar * K + k0 + cb * 8;
            size_t boff = (size_t)(bn + row) * K + k0 + cb * 8;
            uint32_t so = row * TPITCH + cb * 16;
            cp16(sb + so,             Ah + aoff);
            cp16(sb + G64_T + so,     Al + aoff);
            cp16(sb + 2 * G64_T + so, Bh + boff);
            cp16(sb + 3 * G64_T + so, Bl + boff);
        }
        CP_COMMIT();
    };

    load_chunk(0, 0);
    if (NC > 1) load_chunk(1, 1);

    for (int c = 0; c < NC; ++c) {
        if (c + 2 < NC) load_chunk(c + 2, (c + 2) % 3);

        if (c + 2 < NC)      asm volatile("cp.async.wait_group 2;" ::: "memory");
        else if (c + 1 < NC) asm volatile("cp.async.wait_group 1;" ::: "memory");
        else                 asm volatile("cp.async.wait_group 0;" ::: "memory");
        __syncthreads();

        const uint32_t sb  = sbase + (c % 3) * G64_STAGE;
        const uint32_t tAh = sb,             tAl = sb + G64_T;
        const uint32_t tBh = sb + 2 * G64_T, tBl = sb + 3 * G64_T;

#pragma unroll
        for (int ks = 0; ks < 2; ++ks) {
            const int kb = ks * 32;
            uint32_t ah[2][4], al[2][4], bhf[4][2], blf[4][2];
#pragma unroll
            for (int mt = 0; mt < 2; ++mt) {
                uint32_t ro = (wm * 32 + mt * 16 + a_row) * TPITCH + a_kb + kb;
                ldsm4(ah[mt], tAh + ro);
                ldsm4(al[mt], tAl + ro);
            }
#pragma unroll
            for (int nt = 0; nt < 4; ++nt) {
                uint32_t ro = (wn * 32 + nt * 8 + b_row) * TPITCH + b_kb + kb;
                ldsm2(bhf[nt], tBh + ro);
                ldsm2(blf[nt], tBl + ro);
            }
#pragma unroll
            for (int mt = 0; mt < 2; ++mt)
#pragma unroll
                for (int nt = 0; nt < 4; ++nt) {
                    mma16816(acc[mt][nt], ah[mt], bhf[nt]);
                    mma16816(acc[mt][nt], ah[mt], blf[nt]);
                    mma16816(acc[mt][nt], al[mt], bhf[nt]);
                }
        }
        __syncthreads();
    }

    const int r0 = lane >> 2;
    const int q2 = (lane & 3) * 2;
#pragma unroll
    for (int mt = 0; mt < 2; ++mt) {
        int row = bm + wm * 32 + mt * 16 + r0;
#pragma unroll
        for (int nt = 0; nt < 4; ++nt) {
            int col = bn + wn * 32 + nt * 8 + q2;
            float bx = 0.f, by = 0.f;
            if (bias) { bx = bias[col]; by = bias[col + 1]; }
            if (row < M)
                *(float2*)(C + (size_t)row * N + col) =
                    make_float2(acc[mt][nt][0] + bx, acc[mt][nt][1] + by);
            if (row + 8 < M)
                *(float2*)(C + (size_t)(row + 8) * N + col) =
                    make_float2(acc[mt][nt][2] + bx, acc[mt][nt][3] + by);
        }
    }
}

// ---------------------------------------------------------------------------
// Weight packing (fp32 -> split bf16) + biases
// ---------------------------------------------------------------------------
__global__ void pack_weights(const float* __restrict__ wi_w, const float* __restrict__ wi_b,
                             const float* __restrict__ wf_w, const float* __restrict__ wf_b,
                             const float* __restrict__ wo_w, const float* __restrict__ wo_b,
                             const float* __restrict__ wu_w, const float* __restrict__ wu_b) {
    int idx = blockIdx.x * blockDim.x + threadIdx.x;

    if (idx < 2048 * 1024) {
        int r = idx >> 10, k = idx & 1023;
        float v;
        if      (r <  512) v = wi_w[r * 1024 + k];
        else if (r < 1024) v = wo_w[(r -  512) * 1024 + k];
        else if (r < 1536) v = wu_w[(r - 1024) * 1024 + k];
        else               v = (k < 512) ? wf_w[(r - 1536) * 1024 + k] : 0.f;
        split1(v, g_Wnh[idx], g_Wnl[idx]);
    }
    if (idx < 1536 * 512) {
        int r = idx >> 9, k = idx & 511;
        float v;
        if      (r <  512) v = wi_w[r * 1024 + k];
        else if (r < 1024) v = wo_w[(r -  512) * 1024 + k];
        else               v = wu_w[(r - 1024) * 1024 + k];
        split1(v, g_Wlh[idx], g_Wll[idx]);
    }
    if (idx < 512 * 512) {
        int r = idx >> 9, k = idx & 511;
        split1(wf_w[r * 1024 + 512 + k], g_Wfhh[idx], g_Wfhl[idx]);
    }
    if (idx < 1536)
        g_bleaf[idx] = (idx < 512) ? wi_b[idx] : (idx < 1024) ? wo_b[idx - 512] : wu_b[idx - 1024];
    if (idx < 2048)
        g_bnode[idx] = (idx <  512) ? wi_b[idx]
                     : (idx < 1024) ? wo_b[idx -  512]
                     : (idx < 1536) ? wu_b[idx - 1024] : wf_b[idx - 1536];
}

// fp32 -> split bf16, 4 elems/thread
__global__ void split4(const float* __restrict__ src, bf16* __restrict__ h,
                       bf16* __restrict__ l, int n4) {
    int i = blockIdx.x * blockDim.x + threadIdx.x;
    if (i >= n4) return;
    float4 v = ((const float4*)src)[i];
    bf16 hh[4], ll[4];
    split1(v.x, hh[0], ll[0]); split1(v.y, hh[1], ll[1]);
    split1(v.z, hh[2], ll[2]); split1(v.w, hh[3], ll[3]);
    ((uint2*)h)[i] = *(uint2*)hh;
    ((uint2*)l)[i] = *(uint2*)ll;
}

// ---------------------------------------------------------------------------
// Elementwise stages (float4 vectorized)
// ---------------------------------------------------------------------------
__global__ void concat_xh4(const float* __restrict__ x, int off_d, int off_c, int n) {
    int idx = blockIdx.x * blockDim.x + threadIdx.x;
    if (idx >= n * 256) return;
    int r = idx >> 8, c4 = (idx & 255) * 4;
    float4 v;
    if (c4 < 512) {
        v = *(const float4*)(x + (size_t)(off_d + r) * IN_DIM + c4);
    } else {
        int hc = c4 - 512;
        size_t base = (size_t)(off_c + r * 16) * HID + hc;
        v = make_float4(0.f, 0.f, 0.f, 0.f);
#pragma unroll
        for (int k = 0; k < 16; k++) {
            float4 t = *(const float4*)(g_H + base + k * HID);
            v.x += t.x; v.y += t.y; v.z += t.z; v.w += t.w;
        }
    }
    bf16 hh[4], ll[4];
    split1(v.x, hh[0], ll[0]); split1(v.y, hh[1], ll[1]);
    split1(v.z, hh[2], ll[2]); split1(v.w, hh[3], ll[3]);
    size_t o = (size_t)r * 1024 + c4;
    *(uint2*)(g_XHh + o) = *(uint2*)hh;
    *(uint2*)(g_XHl + o) = *(uint2*)ll;
}

__global__ void node_epilogue4(int off_d, int off_c, int n) {
    int idx = blockIdx.x * blockDim.x + threadIdx.x;
    if (idx >= n * 128) return;
    int r = idx >> 7, h4 = (idx & 127) * 4;
    const float* g = g_G + (size_t)r * 2048;
    float4 gi = *(const float4*)(g + h4);
    float4 go = *(const float4*)(g + 512 + h4);
    float4 gu = *(const float4*)(g + 1024 + h4);
    float4 gf = *(const float4*)(g + 1536 + h4);
    float a0 = sigf(gi.x) * tanhf(gu.x);
    float a1 = sigf(gi.y) * tanhf(gu.y);
    float a2 = sigf(gi.z) * tanhf(gu.z);
    float a3 = sigf(gi.w) * tanhf(gu.w);
    size_t cb = (size_t)(off_c + r * 16) * HID + h4;
#pragma unroll
    for (int k = 0; k < 16; k++) {
        float4 fh = *(const float4*)(g_FH + cb + k * HID);
        float4 cc = *(const float4*)(g_C  + cb + k * HID);
        a0 += sigf(gf.x + fh.x) * cc.x;
        a1 += sigf(gf.y + fh.y) * cc.y;
        a2 += sigf(gf.z + fh.z) * cc.z;
        a3 += sigf(gf.w + fh.w) * cc.w;
    }
    size_t gidx = (size_t)(off_d + r) * HID + h4;
    *(float4*)(g_C + gidx) = make_float4(a0, a1, a2, a3);
    float4 hv = make_float4(sigf(go.x) * tanhf(a0), sigf(go.y) * tanhf(a1),
                            sigf(go.z) * tanhf(a2), sigf(go.w) * tanhf(a3));
    *(float4*)(g_H + gidx) = hv;
    bf16 hh[4], ll[4];
    split1(a0, hh[0], ll[0]); split1(a1, hh[1], ll[1]);
    split1(a2, hh[2], ll[2]); split1(a3, hh[3], ll[3]);
    *(uint2*)(g_Ch + gidx) = *(uint2*)hh;
    *(uint2*)(g_Cl + gidx) = *(uint2*)ll;
}

__global__ void writeout(float* __restrict__ out) {
    int idx = blockIdx.x * blockDim.x + threadIdx.x;
    if (idx < 512)       out[idx] = g_H[idx];
    else if (idx < 1024) out[idx] = g_C[idx - 512];
}

// ---------------------------------------------------------------------------
// Launch
// ---------------------------------------------------------------------------
static void launch_gemm(const bf16* Ah, const bf16* Al, const bf16* Bh, const bf16* Bl,
                        float* C, const float* bias, int M, int N, int K) {
    if (M >= 1024) {
        dim3 grid(N / 128, (M + 127) / 128);
        gemm_split<<<grid, 256, GSMEM>>>(Ah, Al, Bh, Bl, C, bias, M, N, K);
    } else {
        dim3 grid(N / 64, (M + 63) / 64);
        gemm_split64<<<grid, 128, G64_SMEM>>>(Ah, Al, Bh, Bl, C, bias, M, N, K);
    }
}

extern "C" void kernel_launch(void* const* d_in, const int* in_sizes, int n_in,
                              void* d_out, int out_size) {
    const float* x    = (const float*)d_in[0];
    const float* wi_w = (const float*)d_in[1];
    const float* wi_b = (const float*)d_in[2];
    const float* wf_w = (const float*)d_in[3];
    const float* wf_b = (const float*)d_in[4];
    const float* wo_w = (const float*)d_in[5];
    const float* wo_b = (const float*)d_in[6];
    const float* wu_w = (const float*)d_in[7];
    const float* wu_b = (const float*)d_in[8];
    float* out = (float*)d_out;

    cudaFuncSetAttribute(gemm_split,   cudaFuncAttributeMaxDynamicSharedMemorySize, GSMEM);
    cudaFuncSetAttribute(gemm_split64, cudaFuncAttributeMaxDynamicSharedMemorySize, G64_SMEM);
    cudaFuncSetAttribute(leaf_fused,   cudaFuncAttributeMaxDynamicSharedMemorySize, LF_SMEM);

    float *pC, *pFH, *pG, *pbn;
    bf16 *pXh, *pXl, *pCh, *pCl, *pXHh, *pXHl, *pWnh, *pWnl, *pWfhh, *pWfhl;
    cudaGetSymbolAddress((void**)&pC,    g_C);
    cudaGetSymbolAddress((void**)&pFH,   g_FH);
    cudaGetSymbolAddress((void**)&pG,    g_G);
    cudaGetSymbolAddress((void**)&pbn,   g_bnode);
    cudaGetSymbolAddress((void**)&pXh,   g_Xh);
    cudaGetSymbolAddress((void**)&pXl,   g_Xl);
    cudaGetSymbolAddress((void**)&pCh,   g_Ch);
    cudaGetSymbolAddress((void**)&pCl,   g_Cl);
    cudaGetSymbolAddress((void**)&pXHh,  g_XHh);
    cudaGetSymbolAddress((void**)&pXHl,  g_XHl);
    cudaGetSymbolAddress((void**)&pWnh,  g_Wnh);
    cudaGetSymbolAddress((void**)&pWnl,  g_Wnl);
    cudaGetSymbolAddress((void**)&pWfhh, g_Wfhh);
    cudaGetSymbolAddress((void**)&pWfhl, g_Wfhl);

    static const int offs[6]  = {0, 1, 17, 273, 4369, 69905};
    static const int sizes[5] = {1, 16, 256, 4096, 65536};

    // 1) weights -> split bf16
    pack_weights<<<(2048 * 1024 + 255) / 256, 256>>>(wi_w, wi_b, wf_w, wf_b,
                                                     wo_w, wo_b, wu_w, wu_b);
    // 2) leaf x -> split bf16
    split4<<<(NLEAF * IN_DIM / 4 + 255) / 256, 256>>>(x + (size_t)offs[4] * IN_DIM,
                                                      pXh, pXl, NLEAF * IN_DIM / 4);
    // 3) fused leaf gates (writes C,H,Ch,Cl), then FH GEMM
    {
        dim3 grid(HID / 64, NLEAF / 128);
        leaf_fused<<<grid, 256, LF_SMEM>>>(pXh, pXl);
    }
    launch_gemm(pCh + (size_t)offs[4] * HID, pCl + (size_t)offs[4] * HID,
                pWfhh, pWfhl, pFH + (size_t)offs[4] * HID, nullptr, NLEAF, 512, 512);

    // 4) internal levels, bottom-up
    for (int d = 3; d >= 0; d--) {
        int n = sizes[d];
        concat_xh4<<<(n * 256 + 255) / 256, 256>>>(x, offs[d], offs[d + 1], n);
        launch_gemm(pXHh, pXHl, pWnh, pWnl, pG, pbn, n, 2048, 1024);
        node_epilogue4<<<(n * 128 + 255) / 256, 256>>>(offs[d], offs[d + 1], n);
        if (d > 0)
            launch_gemm(pCh + (size_t)offs[d] * HID, pCl + (size_t)offs[d] * HID,
                        pWfhh, pWfhl, pFH + (size_t)offs[d] * HID, nullptr, n, 512, 512);
    }

    // 5) output: H[0] then C[0]
    writeout<<<4, 256>>>(out);
}

// round 5
// speedup vs baseline: 2.6752x; 1.0232x over previous
#include <cuda_runtime.h>
#include <cuda_bf16.h>
#include <math.h>
#include <stdint.h>

// ---------------------------------------------------------------------------
// CSTreeLSTM on GB300: split-bf16 HMMA GEMMs (512-thread CTAs, 16 warps),
// fused leaf gate kernel. C = (Ah+Al)(Bh+Bl)^T ~= AhBh + AhBl + AlBh.
// Tree: 16-ary, depth 4, IN=HID=512. Levels 1,16,256,4096,65536
// (offsets 0,1,17,273,4369; total 69905).
// ---------------------------------------------------------------------------

#define IN_DIM 512
#define HID    512
#define NLEAF  65536
#define NTOT   69905

typedef __nv_bfloat16 bf16;

// ------------------------------ device scratch ------------------------------
__device__ __align__(128) float g_C [NTOT * HID];
__device__ __align__(128) float g_H [NTOT * HID];
__device__ __align__(128) float g_FH[NTOT * HID];
__device__ __align__(128) float g_G [4096 * 2048];   // node-level gates only

__device__ __align__(128) bf16 g_Xh [NLEAF * IN_DIM];
__device__ __align__(128) bf16 g_Xl [NLEAF * IN_DIM];
__device__ __align__(128) bf16 g_Ch [NTOT * HID];
__device__ __align__(128) bf16 g_Cl [NTOT * HID];
__device__ __align__(128) bf16 g_XHh[4096 * 1024];
__device__ __align__(128) bf16 g_XHl[4096 * 1024];

__device__ __align__(128) bf16 g_Wnh[2048 * 1024];
__device__ __align__(128) bf16 g_Wnl[2048 * 1024];
__device__ __align__(128) bf16 g_Wlh[1536 * 512];
__device__ __align__(128) bf16 g_Wll[1536 * 512];
__device__ __align__(128) bf16 g_Wfhh[512 * 512];
__device__ __align__(128) bf16 g_Wfhl[512 * 512];
__device__ float g_bleaf[1536];
__device__ float g_bnode[2048];

__device__ __forceinline__ float sigf(float x) { return 1.f / (1.f + expf(-x)); }

__device__ __forceinline__ void split1(float v, bf16& h, bf16& l) {
    h = __float2bfloat16(v);
    l = __float2bfloat16(v - __bfloat162float(h));
}

// ------------------------------ PTX helpers ---------------------------------
__device__ __forceinline__ uint32_t smem_u32(const void* p) {
    uint32_t a;
    asm("{ .reg .u64 t; cvta.to.shared.u64 t, %1; cvt.u32.u64 %0, t; }" : "=r"(a) : "l"(p));
    return a;
}

__device__ __forceinline__ void cp16(uint32_t dst, const void* src) {
    asm volatile("cp.async.cg.shared.global [%0], [%1], 16;" :: "r"(dst), "l"(src));
}
#define CP_COMMIT() asm volatile("cp.async.commit_group;" ::: "memory")

__device__ __forceinline__ void ldsm4(uint32_t* r, uint32_t addr) {
    asm volatile("ldmatrix.sync.aligned.m8n8.x4.shared.b16 {%0,%1,%2,%3}, [%4];"
                 : "=r"(r[0]), "=r"(r[1]), "=r"(r[2]), "=r"(r[3]) : "r"(addr));
}
__device__ __forceinline__ void ldsm2(uint32_t* r, uint32_t addr) {
    asm volatile("ldmatrix.sync.aligned.m8n8.x2.shared.b16 {%0,%1}, [%2];"
                 : "=r"(r[0]), "=r"(r[1]) : "r"(addr));
}
__device__ __forceinline__ void mma16816(float* d, const uint32_t* a, const uint32_t* b) {
    asm volatile(
        "mma.sync.aligned.m16n8k16.row.col.f32.bf16.bf16.f32 "
        "{%0,%1,%2,%3}, {%4,%5,%6,%7}, {%8,%9}, {%0,%1,%2,%3};"
        : "+f"(d[0]), "+f"(d[1]), "+f"(d[2]), "+f"(d[3])
        : "r"(a[0]), "r"(a[1]), "r"(a[2]), "r"(a[3]), "r"(b[0]), "r"(b[1]));
}

// ---------------------------------------------------------------------------
// Fused leaf kernel. CTA tile: 128(M) x 64(h), 3 gates. 512 threads,
// 16 warps, warp tile 32x16 per gate, BK=32, 3 stages. M%128==0, K=512.
// ---------------------------------------------------------------------------
#define LF_PITCH 80
#define LF_AT (128 * LF_PITCH)            // 10240
#define LF_BT (64 * LF_PITCH)             // 5120
#define LF_STAGE (2 * LF_AT + 6 * LF_BT)  // 51200
#define LF_SMEM (3 * LF_STAGE + 128)

__global__ __launch_bounds__(512)
void leaf_fused(const bf16* __restrict__ Ah, const bf16* __restrict__ Al) {
    extern __shared__ char smem_raw[];
    const uint32_t sbase = (smem_u32(smem_raw) + 127) & ~127u;

    const int tid  = threadIdx.x;
    const int lane = tid & 31;
    const int wid  = tid >> 5;             // 0..15
    const int wm   = wid >> 2;             // 0..3 (M slices of 32)
    const int wn   = wid & 3;              // 0..3 (h slices of 16)
    const int bm   = blockIdx.y * 128;
    const int bh   = blockIdx.x * 64;
    const int K    = 512;
    const int NC   = 16;

    const int ag = lane >> 3, ai = lane & 7;
    const int a_row = ai + (ag & 1) * 8;
    const int a_kb  = (ag >> 1) * 16;
    const int b_row = lane & 7;
    const int b_kb  = ((lane >> 3) & 1) * 16;

    float acc[3][2][2][4];
#pragma unroll
    for (int g = 0; g < 3; g++)
#pragma unroll
        for (int mt = 0; mt < 2; mt++)
#pragma unroll
            for (int nt = 0; nt < 2; nt++)
#pragma unroll
                for (int j = 0; j < 4; j++) acc[g][mt][nt][j] = 0.f;

    auto load_chunk = [&](int c, int s) {
        const uint32_t sb = sbase + s * LF_STAGE;
        const int k0 = c << 5;
        {   // A: 2 tiles x 512 chunks = 1024; 2 per thread
            int row = tid >> 2, cb = tid & 3;
            size_t aoff = (size_t)(bm + row) * K + k0 + cb * 8;
            uint32_t so = row * LF_PITCH + cb * 16;
            cp16(sb + so,         Ah + aoff);
            cp16(sb + LF_AT + so, Al + aoff);
        }
        // B: 3 gate pairs x 256 positions = 768; <=2 per thread
#pragma unroll
        for (int i = 0; i < 2; ++i) {
            int p = tid + i * 512;
            if (p < 768) {
                int g = p >> 8, pp = p & 255;
                int row = pp >> 2, cb = pp & 3;
                size_t woff = (size_t)(g * 512 + bh + row) * 512 + k0 + cb * 8;
                uint32_t base = sb + 2 * LF_AT + g * 2 * LF_BT;
                uint32_t so = row * LF_PITCH + cb * 16;
                cp16(base + so,         g_Wlh + woff);
                cp16(base + LF_BT + so, g_Wll + woff);
            }
        }
        CP_COMMIT();
    };

    load_chunk(0, 0);
    load_chunk(1, 1);

    for (int c = 0; c < NC; ++c) {
        if (c + 2 < NC) load_chunk(c + 2, (c + 2) % 3);

        if (c + 2 < NC)      asm volatile("cp.async.wait_group 2;" ::: "memory");
        else if (c + 1 < NC) asm volatile("cp.async.wait_group 1;" ::: "memory");
        else                 asm volatile("cp.async.wait_group 0;" ::: "memory");
        __syncthreads();

        const uint32_t sb = sbase + (c % 3) * LF_STAGE;

#pragma unroll
        for (int ks = 0; ks < 2; ++ks) {
            const int kb = ks * 32;
            uint32_t ah[2][4], al[2][4];
#pragma unroll
            for (int mt = 0; mt < 2; ++mt) {
                uint32_t ro = (wm * 32 + mt * 16 + a_row) * LF_PITCH + a_kb + kb;
                ldsm4(ah[mt], sb + ro);
                ldsm4(al[mt], sb + LF_AT + ro);
            }
#pragma unroll
            for (int g = 0; g < 3; ++g) {
                const uint32_t base = sb + 2 * LF_AT + g * 2 * LF_BT;
                uint32_t bhf[2][2], blf[2][2];
#pragma unroll
                for (int nt = 0; nt < 2; ++nt) {
                    uint32_t ro = (wn * 16 + nt * 8 + b_row) * LF_PITCH + b_kb + kb;
                    ldsm2(bhf[nt], base + ro);
                    ldsm2(blf[nt], base + LF_BT + ro);
                }
#pragma unroll
                for (int mt = 0; mt < 2; ++mt)
#pragma unroll
                    for (int nt = 0; nt < 2; ++nt) {
                        mma16816(acc[g][mt][nt], ah[mt], bhf[nt]);
                        mma16816(acc[g][mt][nt], ah[mt], blf[nt]);
                        mma16816(acc[g][mt][nt], al[mt], bhf[nt]);
                    }
            }
        }
        __syncthreads();
    }

    // epilogue: gates -> C,H,Ch,Cl
    const int r0 = lane >> 2;
    const int q2 = (lane & 3) * 2;
#pragma unroll
    for (int mt = 0; mt < 2; ++mt) {
#pragma unroll
        for (int nt = 0; nt < 2; ++nt) {
            int col = bh + wn * 16 + nt * 8 + q2;
            float bi0 = g_bleaf[col],        bi1 = g_bleaf[col + 1];
            float bo0 = g_bleaf[512 + col],  bo1 = g_bleaf[512 + col + 1];
            float bu0 = g_bleaf[1024 + col], bu1 = g_bleaf[1024 + col + 1];
#pragma unroll
            for (int hf = 0; hf < 2; ++hf) {
                int row = bm + wm * 32 + mt * 16 + r0 + hf * 8;
                float i0 = sigf(acc[0][mt][nt][hf * 2 + 0] + bi0);
                float i1 = sigf(acc[0][mt][nt][hf * 2 + 1] + bi1);
                float o0 = sigf(acc[1][mt][nt][hf * 2 + 0] + bo0);
                float o1 = sigf(acc[1][mt][nt][hf * 2 + 1] + bo1);
                float u0 = tanhf(acc[2][mt][nt][hf * 2 + 0] + bu0);
                float u1 = tanhf(acc[2][mt][nt][hf * 2 + 1] + bu1);
                float c0 = i0 * u0, c1 = i1 * u1;
                float h0 = o0 * tanhf(c0), h1 = o1 * tanhf(c1);
                size_t gi = (size_t)(4369 + row) * HID + col;
                *(float2*)(g_C + gi) = make_float2(c0, c1);
                *(float2*)(g_H + gi) = make_float2(h0, h1);
                bf16 hh0, ll0, hh1, ll1;
                split1(c0, hh0, ll0); split1(c1, hh1, ll1);
                __nv_bfloat162 vh; vh.x = hh0; vh.y = hh1;
                __nv_bfloat162 vl; vl.x = ll0; vl.y = ll1;
                *(__nv_bfloat162*)(g_Ch + gi) = vh;
                *(__nv_bfloat162*)(g_Cl + gi) = vl;
            }
        }
    }
}

// ---------------------------------------------------------------------------
// Split-bf16 GEMM, CTA 128x128, 512 threads / 16 warps, warp tile 32x32,
// BK=32, 3-stage cp.async. N%128==0, K%32==0; M guarded.
// ---------------------------------------------------------------------------
#define TPITCH 80
#define TILE_B (128 * TPITCH)
#define STAGE_B (4 * TILE_B)
#define GSMEM (3 * STAGE_B + 128)

__global__ __launch_bounds__(512)
void gemm_split(const bf16* __restrict__ Ah, const bf16* __restrict__ Al,
                const bf16* __restrict__ Bh, const bf16* __restrict__ Bl,
                float* __restrict__ C, const float* __restrict__ bias,
                int M, int N, int K) {
    extern __shared__ char smem_raw[];
    const uint32_t sbase = (smem_u32(smem_raw) + 127) & ~127u;

    const int tid  = threadIdx.x;
    const int lane = tid & 31;
    const int wid  = tid >> 5;          // 0..15
    const int wm   = wid >> 2;          // 0..3
    const int wn   = wid & 3;           // 0..3
    const int bm   = blockIdx.y * 128;
    const int bn   = blockIdx.x * 128;
    const int NC   = K >> 5;

    const int ag = lane >> 3, ai = lane & 7;
    const int a_row = ai + (ag & 1) * 8;
    const int a_kb  = (ag >> 1) * 16;
    const int b_row = lane & 7;
    const int b_kb  = ((lane >> 3) & 1) * 16;

    float acc[2][4][4];
#pragma unroll
    for (int mt = 0; mt < 2; mt++)
#pragma unroll
        for (int nt = 0; nt < 4; nt++)
#pragma unroll
            for (int j = 0; j < 4; j++) acc[mt][nt][j] = 0.f;

    auto load_chunk = [&](int c, int s) {
        const uint32_t sb = sbase + s * STAGE_B;
        const int k0 = c << 5;
        int row = tid >> 2, cb = tid & 3;          // 512 thr = 512 chunks/tile
        int ar = bm + row; if (ar > M - 1) ar = M - 1;
        size_t aoff = (size_t)ar * K + k0 + cb * 8;
        size_t boff = (size_t)(bn + row) * K + k0 + cb * 8;
        uint32_t so = row * TPITCH + cb * 16;
        cp16(sb + so,              Ah + aoff);
        cp16(sb + TILE_B + so,     Al + aoff);
        cp16(sb + 2 * TILE_B + so, Bh + boff);
        cp16(sb + 3 * TILE_B + so, Bl + boff);
        CP_COMMIT();
    };

    load_chunk(0, 0);
    if (NC > 1) load_chunk(1, 1);

    for (int c = 0; c < NC; ++c) {
        if (c + 2 < NC) load_chunk(c + 2, (c + 2) % 3);

        if (c + 2 < NC)      asm volatile("cp.async.wait_group 2;" ::: "memory");
        else if (c + 1 < NC) asm volatile("cp.async.wait_group 1;" ::: "memory");
        else                 asm volatile("cp.async.wait_group 0;" ::: "memory");
        __syncthreads();

        const uint32_t sb  = sbase + (c % 3) * STAGE_B;
        const uint32_t tAh = sb,              tAl = sb + TILE_B;
        const uint32_t tBh = sb + 2 * TILE_B, tBl = sb + 3 * TILE_B;

#pragma unroll
        for (int ks = 0; ks < 2; ++ks) {
            const int kb = ks * 32;
            uint32_t ah[2][4], al[2][4], bhf[4][2], blf[4][2];
#pragma unroll
            for (int mt = 0; mt < 2; ++mt) {
                uint32_t ro = (wm * 32 + mt * 16 + a_row) * TPITCH + a_kb + kb;
                ldsm4(ah[mt], tAh + ro);
                ldsm4(al[mt], tAl + ro);
            }
#pragma unroll
            for (int nt = 0; nt < 4; ++nt) {
                uint32_t ro = (wn * 32 + nt * 8 + b_row) * TPITCH + b_kb + kb;
                ldsm2(bhf[nt], tBh + ro);
                ldsm2(blf[nt], tBl + ro);
            }
#pragma unroll
            for (int mt = 0; mt < 2; ++mt)
#pragma unroll
                for (int nt = 0; nt < 4; ++nt) {
                    mma16816(acc[mt][nt], ah[mt], bhf[nt]);
                    mma16816(acc[mt][nt], ah[mt], blf[nt]);
                    mma16816(acc[mt][nt], al[mt], bhf[nt]);
                }
        }
        __syncthreads();
    }

    const int r0 = lane >> 2;
    const int q2 = (lane & 3) * 2;
#pragma unroll
    for (int mt = 0; mt < 2; ++mt) {
        int row = bm + wm * 32 + mt * 16 + r0;
#pragma unroll
        for (int nt = 0; nt < 4; ++nt) {
            int col = bn + wn * 32 + nt * 8 + q2;
            float bx = 0.f, by = 0.f;
            if (bias) { bx = bias[col]; by = bias[col + 1]; }
            if (row < M)
                *(float2*)(C + (size_t)row * N + col) =
                    make_float2(acc[mt][nt][0] + bx, acc[mt][nt][1] + by);
            if (row + 8 < M)
                *(float2*)(C + (size_t)(row + 8) * N + col) =
                    make_float2(acc[mt][nt][2] + bx, acc[mt][nt][3] + by);
        }
    }
}

// ---------------------------------------------------------------------------
// Split-bf16 GEMM, CTA 64x64 (small M tail). 128 threads, 4 warps 32x32.
// ---------------------------------------------------------------------------
#define G64_T (64 * TPITCH)
#define G64_STAGE (4 * G64_T)
#define G64_SMEM (3 * G64_STAGE + 128)

__global__ __launch_bounds__(128)
void gemm_split64(const bf16* __restrict__ Ah, const bf16* __restrict__ Al,
                  const bf16* __restrict__ Bh, const bf16* __restrict__ Bl,
                  float* __restrict__ C, const float* __restrict__ bias,
                  int M, int N, int K) {
    extern __shared__ char smem_raw[];
    const uint32_t sbase = (smem_u32(smem_raw) + 127) & ~127u;

    const int tid  = threadIdx.x;
    const int lane = tid & 31;
    const int wid  = tid >> 5;
    const int wm   = wid >> 1;
    const int wn   = wid & 1;
    const int bm   = blockIdx.y * 64;
    const int bn   = blockIdx.x * 64;
    const int NC   = K >> 5;

    const int ag = lane >> 3, ai = lane & 7;
    const int a_row = ai + (ag & 1) * 8;
    const int a_kb  = (ag >> 1) * 16;
    const int b_row = lane & 7;
    const int b_kb  = ((lane >> 3) & 1) * 16;

    float acc[2][4][4];
#pragma unroll
    for (int mt = 0; mt < 2; mt++)
#pragma unroll
        for (int nt = 0; nt < 4; nt++)
#pragma unroll
            for (int j = 0; j < 4; j++) acc[mt][nt][j] = 0.f;

    auto load_chunk = [&](int c, int s) {
        const uint32_t sb = sbase + s * G64_STAGE;
        const int k0 = c << 5;
#pragma unroll
        for (int it = 0; it < 2; ++it) {
            int idx = tid + it * 128;
            int row = idx >> 2, cb = idx & 3;
            int ar = bm + row; if (ar > M - 1) ar = M - 1;
            size_t aoff = (size_t)ar * K + k0 + cb * 8;
            size_t boff = (size_t)(bn + row) * K + k0 + cb * 8;
            uint32_t so = row * TPITCH + cb * 16;
            cp16(sb + so,             Ah + aoff);
            cp16(sb + G64_T + so,     Al + aoff);
            cp16(sb + 2 * G64_T + so, Bh + boff);
            cp16(sb + 3 * G64_T + so, Bl + boff);
        }
        CP_COMMIT();
    };

    load_chunk(0, 0);
    if (NC > 1) load_chunk(1, 1);

    for (int c = 0; c < NC; ++c) {
        if (c + 2 < NC) load_chunk(c + 2, (c + 2) % 3);

        if (c + 2 < NC)      asm volatile("cp.async.wait_group 2;" ::: "memory");
        else if (c + 1 < NC) asm volatile("cp.async.wait_group 1;" ::: "memory");
        else                 asm volatile("cp.async.wait_group 0;" ::: "memory");
        __syncthreads();

        const uint32_t sb  = sbase + (c % 3) * G64_STAGE;
        const uint32_t tAh = sb,             tAl = sb + G64_T;
        const uint32_t tBh = sb + 2 * G64_T, tBl = sb + 3 * G64_T;

#pragma unroll
        for (int ks = 0; ks < 2; ++ks) {
            const int kb = ks * 32;
            uint32_t ah[2][4], al[2][4], bhf[4][2], blf[4][2];
#pragma unroll
            for (int mt = 0; mt < 2; ++mt) {
                uint32_t ro = (wm * 32 + mt * 16 + a_row) * TPITCH + a_kb + kb;
                ldsm4(ah[mt], tAh + ro);
                ldsm4(al[mt], tAl + ro);
            }
#pragma unroll
            for (int nt = 0; nt < 4; ++nt) {
                uint32_t ro = (wn * 32 + nt * 8 + b_row) * TPITCH + b_kb + kb;
                ldsm2(bhf[nt], tBh + ro);
                ldsm2(blf[nt], tBl + ro);
            }
#pragma unroll
            for (int mt = 0; mt < 2; ++mt)
#pragma unroll
                for (int nt = 0; nt < 4; ++nt) {
                    mma16816(acc[mt][nt], ah[mt], bhf[nt]);
                    mma16816(acc[mt][nt], ah[mt], blf[nt]);
                    mma16816(acc[mt][nt], al[mt], bhf[nt]);
                }
        }
        __syncthreads();
    }

    const int r0 = lane >> 2;
    const int q2 = (lane & 3) * 2;
#pragma unroll
    for (int mt = 0; mt < 2; ++mt) {
        int row = bm + wm * 32 + mt * 16 + r0;
#pragma unroll
        for (int nt = 0; nt < 4; ++nt) {
            int col = bn + wn * 32 + nt * 8 + q2;
            float bx = 0.f, by = 0.f;
            if (bias) { bx = bias[col]; by = bias[col + 1]; }
            if (row < M)
                *(float2*)(C + (size_t)row * N + col) =
                    make_float2(acc[mt][nt][0] + bx, acc[mt][nt][1] + by);
            if (row + 8 < M)
                *(float2*)(C + (size_t)(row + 8) * N + col) =
                    make_float2(acc[mt][nt][2] + bx, acc[mt][nt][3] + by);
        }
    }
}

// ---------------------------------------------------------------------------
// Weight packing (fp32 -> split bf16) + biases
// ---------------------------------------------------------------------------
__global__ void pack_weights(const float* __restrict__ wi_w, const float* __restrict__ wi_b,
                             const float* __restrict__ wf_w, const float* __restrict__ wf_b,
                             const float* __restrict__ wo_w, const float* __restrict__ wo_b,
                             const float* __restrict__ wu_w, const float* __restrict__ wu_b) {
    int idx = blockIdx.x * blockDim.x + threadIdx.x;

    if (idx < 2048 * 1024) {
        int r = idx >> 10, k = idx & 1023;
        float v;
        if      (r <  512) v = wi_w[r * 1024 + k];
        else if (r < 1024) v = wo_w[(r -  512) * 1024 + k];
        else if (r < 1536) v = wu_w[(r - 1024) * 1024 + k];
        else               v = (k < 512) ? wf_w[(r - 1536) * 1024 + k] : 0.f;
        split1(v, g_Wnh[idx], g_Wnl[idx]);
    }
    if (idx < 1536 * 512) {
        int r = idx >> 9, k = idx & 511;
        float v;
        if      (r <  512) v = wi_w[r * 1024 + k];
        else if (r < 1024) v = wo_w[(r -  512) * 1024 + k];
        else               v = wu_w[(r - 1024) * 1024 + k];
        split1(v, g_Wlh[idx], g_Wll[idx]);
    }
    if (idx < 512 * 512) {
        int r = idx >> 9, k = idx & 511;
        split1(wf_w[r * 1024 + 512 + k], g_Wfhh[idx], g_Wfhl[idx]);
    }
    if (idx < 1536)
        g_bleaf[idx] = (idx < 512) ? wi_b[idx] : (idx < 1024) ? wo_b[idx - 512] : wu_b[idx - 1024];
    if (idx < 2048)
        g_bnode[idx] = (idx <  512) ? wi_b[idx]
                     : (idx < 1024) ? wo_b[idx -  512]
                     : (idx < 1536) ? wu_b[idx - 1024] : wf_b[idx - 1536];
}

// fp32 -> split bf16, 4 elems/thread
__global__ void split4(const float* __restrict__ src, bf16* __restrict__ h,
                       bf16* __restrict__ l, int n4) {
    int i = blockIdx.x * blockDim.x + threadIdx.x;
    if (i >= n4) return;
    float4 v = ((const float4*)src)[i];
    bf16 hh[4], ll[4];
    split1(v.x, hh[0], ll[0]); split1(v.y, hh[1], ll[1]);
    split1(v.z, hh[2], ll[2]); split1(v.w, hh[3], ll[3]);
    ((uint2*)h)[i] = *(uint2*)hh;
    ((uint2*)l)[i] = *(uint2*)ll;
}

// ---------------------------------------------------------------------------
// Elementwise stages (float4 vectorized)
// ---------------------------------------------------------------------------
__global__ void concat_xh4(const float* __restrict__ x, int off_d, int off_c, int n) {
    int idx = blockIdx.x * blockDim.x + threadIdx.x;
    if (idx >= n * 256) return;
    int r = idx >> 8, c4 = (idx & 255) * 4;
    float4 v;
    if (c4 < 512) {
        v = *(const float4*)(x + (size_t)(off_d + r) * IN_DIM + c4);
    } else {
        int hc = c4 - 512;
        size_t base = (size_t)(off_c + r * 16) * HID + hc;
        v = make_float4(0.f, 0.f, 0.f, 0.f);
#pragma unroll
        for (int k = 0; k < 16; k++) {
            float4 t = *(const float4*)(g_H + base + k * HID);
            v.x += t.x; v.y += t.y; v.z += t.z; v.w += t.w;
        }
    }
    bf16 hh[4], ll[4];
    split1(v.x, hh[0], ll[0]); split1(v.y, hh[1], ll[1]);
    split1(v.z, hh[2], ll[2]); split1(v.w, hh[3], ll[3]);
    size_t o = (size_t)r * 1024 + c4;
    *(uint2*)(g_XHh + o) = *(uint2*)hh;
    *(uint2*)(g_XHl + o) = *(uint2*)ll;
}

__global__ void node_epilogue4(int off_d, int off_c, int n) {
    int idx = blockIdx.x * blockDim.x + threadIdx.x;
    if (idx >= n * 128) return;
    int r = idx >> 7, h4 = (idx & 127) * 4;
    const float* g = g_G + (size_t)r * 2048;
    float4 gi = *(const float4*)(g + h4);
    float4 go = *(const float4*)(g + 512 + h4);
    float4 gu = *(const float4*)(g + 1024 + h4);
    float4 gf = *(const float4*)(g + 1536 + h4);
    float a0 = sigf(gi.x) * tanhf(gu.x);
    float a1 = sigf(gi.y) * tanhf(gu.y);
    float a2 = sigf(gi.z) * tanhf(gu.z);
    float a3 = sigf(gi.w) * tanhf(gu.w);
    size_t cb = (size_t)(off_c + r * 16) * HID + h4;
#pragma unroll
    for (int k = 0; k < 16; k++) {
        float4 fh = *(const float4*)(g_FH + cb + k * HID);
        float4 cc = *(const float4*)(g_C  + cb + k * HID);
        a0 += sigf(gf.x + fh.x) * cc.x;
        a1 += sigf(gf.y + fh.y) * cc.y;
        a2 += sigf(gf.z + fh.z) * cc.z;
        a3 += sigf(gf.w + fh.w) * cc.w;
    }
    size_t gidx = (size_t)(off_d + r) * HID + h4;
    *(float4*)(g_C + gidx) = make_float4(a0, a1, a2, a3);
    float4 hv = make_float4(sigf(go.x) * tanhf(a0), sigf(go.y) * tanhf(a1),
                            sigf(go.z) * tanhf(a2), sigf(go.w) * tanhf(a3));
    *(float4*)(g_H + gidx) = hv;
    bf16 hh[4], ll[4];
    split1(a0, hh[0], ll[0]); split1(a1, hh[1], ll[1]);
    split1(a2, hh[2], ll[2]); split1(a3, hh[3], ll[3]);
    *(uint2*)(g_Ch + gidx) = *(uint2*)hh;
    *(uint2*)(g_Cl + gidx) = *(uint2*)ll;
}

__global__ void writeout(float* __restrict__ out) {
    int idx = blockIdx.x * blockDim.x + threadIdx.x;
    if (idx < 512)       out[idx] = g_H[idx];
    else if (idx < 1024) out[idx] = g_C[idx - 512];
}

// ---------------------------------------------------------------------------
// Launch
// ---------------------------------------------------------------------------
static void launch_gemm(const bf16* Ah, const bf16* Al, const bf16* Bh, const bf16* Bl,
                        float* C, const float* bias, int M, int N, int K) {
    if (M >= 1024) {
        dim3 grid(N / 128, (M + 127) / 128);
        gemm_split<<<grid, 512, GSMEM>>>(Ah, Al, Bh, Bl, C, bias, M, N, K);
    } else {
        dim3 grid(N / 64, (M + 63) / 64);
        gemm_split64<<<grid, 128, G64_SMEM>>>(Ah, Al, Bh, Bl, C, bias, M, N, K);
    }
}

extern "C" void kernel_launch(void* const* d_in, const int* in_sizes, int n_in,
                              void* d_out, int out_size) {
    const float* x    = (const float*)d_in[0];
    const float* wi_w = (const float*)d_in[1];
    const float* wi_b = (const float*)d_in[2];
    const float* wf_w = (const float*)d_in[3];
    const float* wf_b = (const float*)d_in[4];
    const float* wo_w = (const float*)d_in[5];
    const float* wo_b = (const float*)d_in[6];
    const float* wu_w = (const float*)d_in[7];
    const float* wu_b = (const float*)d_in[8];
    float* out = (float*)d_out;

    cudaFuncSetAttribute(gemm_split,   cudaFuncAttributeMaxDynamicSharedMemorySize, GSMEM);
    cudaFuncSetAttribute(gemm_split64, cudaFuncAttributeMaxDynamicSharedMemorySize, G64_SMEM);
    cudaFuncSetAttribute(leaf_fused,   cudaFuncAttributeMaxDynamicSharedMemorySize, LF_SMEM);

    float *pC, *pFH, *pG, *pbn;
    bf16 *pXh, *pXl, *pCh, *pCl, *pXHh, *pXHl, *pWnh, *pWnl, *pWfhh, *pWfhl;
    cudaGetSymbolAddress((void**)&pC,    g_C);
    cudaGetSymbolAddress((void**)&pFH,   g_FH);
    cudaGetSymbolAddress((void**)&pG,    g_G);
    cudaGetSymbolAddress((void**)&pbn,   g_bnode);
    cudaGetSymbolAddress((void**)&pXh,   g_Xh);
    cudaGetSymbolAddress((void**)&pXl,   g_Xl);
    cudaGetSymbolAddress((void**)&pCh,   g_Ch);
    cudaGetSymbolAddress((void**)&pCl,   g_Cl);
    cudaGetSymbolAddress((void**)&pXHh,  g_XHh);
    cudaGetSymbolAddress((void**)&pXHl,  g_XHl);
    cudaGetSymbolAddress((void**)&pWnh,  g_Wnh);
    cudaGetSymbolAddress((void**)&pWnl,  g_Wnl);
    cudaGetSymbolAddress((void**)&pWfhh, g_Wfhh);
    cudaGetSymbolAddress((void**)&pWfhl, g_Wfhl);

    static const int offs[6]  = {0, 1, 17, 273, 4369, 69905};
    static const int sizes[5] = {1, 16, 256, 4096, 65536};

    // 1) weights -> split bf16
    pack_weights<<<(2048 * 1024 + 255) / 256, 256>>>(wi_w, wi_b, wf_w, wf_b,
                                                     wo_w, wo_b, wu_w, wu_b);
    // 2) leaf x -> split bf16
    split4<<<(NLEAF * IN_DIM / 4 + 255) / 256, 256>>>(x + (size_t)offs[4] * IN_DIM,
                                                      pXh, pXl, NLEAF * IN_DIM / 4);
    // 3) fused leaf gates (writes C,H,Ch,Cl), then FH GEMM
    {
        dim3 grid(HID / 64, NLEAF / 128);
        leaf_fused<<<grid, 512, LF_SMEM>>>(pXh, pXl);
    }
    launch_gemm(pCh + (size_t)offs[4] * HID, pCl + (size_t)offs[4] * HID,
                pWfhh, pWfhl, pFH + (size_t)offs[4] * HID, nullptr, NLEAF, 512, 512);

    // 4) internal levels, bottom-up
    for (int d = 3; d >= 0; d--) {
        int n = sizes[d];
        concat_xh4<<<(n * 256 + 255) / 256, 256>>>(x, offs[d], offs[d + 1], n);
        launch_gemm(pXHh, pXHl, pWnh, pWnl, pG, pbn, n, 2048, 1024);
        node_epilogue4<<<(n * 128 + 255) / 256, 256>>>(offs[d], offs[d + 1], n);
        if (d > 0)
            launch_gemm(pCh + (size_t)offs[d] * HID, pCl + (size_t)offs[d] * HID,
                        pWfhh, pWfhl, pFH + (size_t)offs[d] * HID, nullptr, n, 512, 512);
    }

    // 5) output: H[0] then C[0]
    writeout<<<4, 256>>>(out);
}

// round 6
// speedup vs baseline: 2.7205x; 1.0169x over previous
#include <cuda_runtime.h>
#include <cuda_fp16.h>
#include <math.h>
#include <stdint.h>

// ---------------------------------------------------------------------------
// CSTreeLSTM on GB300: split-fp16 HMMA GEMMs. C = (Ah+Al)(Bh+Bl)^T
// ~= AhBh + AhBl + AlBh  (AlBl ~ 2^-22, dropped).
// Tree: 16-ary, depth 4, IN=HID=512. Levels 1,16,256,4096,65536
// (offsets 0,1,17,273,4369; total 69905).
// ---------------------------------------------------------------------------

#define IN_DIM 512
#define HID    512
#define NLEAF  65536
#define NTOT   69905

typedef __half hlf;

// ------------------------------ device scratch ------------------------------
__device__ __align__(128) float g_C [NTOT * HID];
__device__ __align__(128) float g_H [NTOT * HID];
__device__ __align__(128) float g_FH[NTOT * HID];
__device__ __align__(128) float g_G [4096 * 2048];   // node-level gates only

__device__ __align__(128) hlf g_Xh [NLEAF * IN_DIM];
__device__ __align__(128) hlf g_Xl [NLEAF * IN_DIM];
__device__ __align__(128) hlf g_Ch [NTOT * HID];
__device__ __align__(128) hlf g_Cl [NTOT * HID];
__device__ __align__(128) hlf g_XHh[4096 * 1024];
__device__ __align__(128) hlf g_XHl[4096 * 1024];

__device__ __align__(128) hlf g_Wnh[2048 * 1024];
__device__ __align__(128) hlf g_Wnl[2048 * 1024];
__device__ __align__(128) hlf g_Wlh[1536 * 512];
__device__ __align__(128) hlf g_Wll[1536 * 512];
__device__ __align__(128) hlf g_Wfhh[512 * 512];
__device__ __align__(128) hlf g_Wfhl[512 * 512];
__device__ float g_bleaf[1536];
__device__ float g_bnode[2048];

__device__ __forceinline__ float sigf(float x) { return 1.f / (1.f + expf(-x)); }

__device__ __forceinline__ void split1(float v, hlf& h, hlf& l) {
    h = __float2half_rn(v);
    l = __float2half_rn(v - __half2float(h));
}

// ------------------------------ PTX helpers ---------------------------------
__device__ __forceinline__ uint32_t smem_u32(const void* p) {
    uint32_t a;
    asm("{ .reg .u64 t; cvta.to.shared.u64 t, %1; cvt.u32.u64 %0, t; }" : "=r"(a) : "l"(p));
    return a;
}

__device__ __forceinline__ void cp16(uint32_t dst, const void* src) {
    asm volatile("cp.async.cg.shared.global [%0], [%1], 16;" :: "r"(dst), "l"(src));
}
#define CP_COMMIT() asm volatile("cp.async.commit_group;" ::: "memory")

__device__ __forceinline__ void ldsm4(uint32_t* r, uint32_t addr) {
    asm volatile("ldmatrix.sync.aligned.m8n8.x4.shared.b16 {%0,%1,%2,%3}, [%4];"
                 : "=r"(r[0]), "=r"(r[1]), "=r"(r[2]), "=r"(r[3]) : "r"(addr));
}
__device__ __forceinline__ void ldsm2(uint32_t* r, uint32_t addr) {
    asm volatile("ldmatrix.sync.aligned.m8n8.x2.shared.b16 {%0,%1}, [%2];"
                 : "=r"(r[0]), "=r"(r[1]) : "r"(addr));
}
__device__ __forceinline__ void mma16816(float* d, const uint32_t* a, const uint32_t* b) {
    asm volatile(
        "mma.sync.aligned.m16n8k16.row.col.f32.f16.f16.f32 "
        "{%0,%1,%2,%3}, {%4,%5,%6,%7}, {%8,%9}, {%0,%1,%2,%3};"
        : "+f"(d[0]), "+f"(d[1]), "+f"(d[2]), "+f"(d[3])
        : "r"(a[0]), "r"(a[1]), "r"(a[2]), "r"(a[3]), "r"(b[0]), "r"(b[1]));
}

// ---------------------------------------------------------------------------
// Fused leaf kernel. CTA tile: 128(M) x 64(h), 3 gates. 512 threads,
// 16 warps, warp tile 32x16 per gate, BK=32, 3 stages. M%128==0, K=512.
// ---------------------------------------------------------------------------
#define LF_PITCH 80
#define LF_AT (128 * LF_PITCH)
#define LF_BT (64 * LF_PITCH)
#define LF_STAGE (2 * LF_AT + 6 * LF_BT)
#define LF_SMEM (3 * LF_STAGE + 128)

__global__ __launch_bounds__(512)
void leaf_fused(const hlf* __restrict__ Ah, const hlf* __restrict__ Al) {
    extern __shared__ char smem_raw[];
    const uint32_t sbase = (smem_u32(smem_raw) + 127) & ~127u;

    const int tid  = threadIdx.x;
    const int lane = tid & 31;
    const int wid  = tid >> 5;
    const int wm   = wid >> 2;
    const int wn   = wid & 3;
    const int bm   = blockIdx.y * 128;
    const int bh   = blockIdx.x * 64;
    const int K    = 512;
    const int NC   = 16;

    const int ag = lane >> 3, ai = lane & 7;
    const int a_row = ai + (ag & 1) * 8;
    const int a_kb  = (ag >> 1) * 16;
    const int b_row = lane & 7;
    const int b_kb  = ((lane >> 3) & 1) * 16;

    float acc[3][2][2][4];
#pragma unroll
    for (int g = 0; g < 3; g++)
#pragma unroll
        for (int mt = 0; mt < 2; mt++)
#pragma unroll
            for (int nt = 0; nt < 2; nt++)
#pragma unroll
                for (int j = 0; j < 4; j++) acc[g][mt][nt][j] = 0.f;

    auto load_chunk = [&](int c, int s) {
        const uint32_t sb = sbase + s * LF_STAGE;
        const int k0 = c << 5;
        {
            int row = tid >> 2, cb = tid & 3;
            size_t aoff = (size_t)(bm + row) * K + k0 + cb * 8;
            uint32_t so = row * LF_PITCH + cb * 16;
            cp16(sb + so,         Ah + aoff);
            cp16(sb + LF_AT + so, Al + aoff);
        }
#pragma unroll
        for (int i = 0; i < 2; ++i) {
            int p = tid + i * 512;
            if (p < 768) {
                int g = p >> 8, pp = p & 255;
                int row = pp >> 2, cb = pp & 3;
                size_t woff = (size_t)(g * 512 + bh + row) * 512 + k0 + cb * 8;
                uint32_t base = sb + 2 * LF_AT + g * 2 * LF_BT;
                uint32_t so = row * LF_PITCH + cb * 16;
                cp16(base + so,         g_Wlh + woff);
                cp16(base + LF_BT + so, g_Wll + woff);
            }
        }
        CP_COMMIT();
    };

    load_chunk(0, 0);
    load_chunk(1, 1);

    for (int c = 0; c < NC; ++c) {
        if (c + 2 < NC) load_chunk(c + 2, (c + 2) % 3);

        if (c + 2 < NC)      asm volatile("cp.async.wait_group 2;" ::: "memory");
        else if (c + 1 < NC) asm volatile("cp.async.wait_group 1;" ::: "memory");
        else                 asm volatile("cp.async.wait_group 0;" ::: "memory");
        __syncthreads();

        const uint32_t sb = sbase + (c % 3) * LF_STAGE;

#pragma unroll
        for (int ks = 0; ks < 2; ++ks) {
            const int kb = ks * 32;
            uint32_t ah[2][4], al[2][4];
#pragma unroll
            for (int mt = 0; mt < 2; ++mt) {
                uint32_t ro = (wm * 32 + mt * 16 + a_row) * LF_PITCH + a_kb + kb;
                ldsm4(ah[mt], sb + ro);
                ldsm4(al[mt], sb + LF_AT + ro);
            }
#pragma unroll
            for (int g = 0; g < 3; ++g) {
                const uint32_t base = sb + 2 * LF_AT + g * 2 * LF_BT;
                uint32_t bhf[2][2], blf[2][2];
#pragma unroll
                for (int nt = 0; nt < 2; ++nt) {
                    uint32_t ro = (wn * 16 + nt * 8 + b_row) * LF_PITCH + b_kb + kb;
                    ldsm2(bhf[nt], base + ro);
                    ldsm2(blf[nt], base + LF_BT + ro);
                }
#pragma unroll
                for (int mt = 0; mt < 2; ++mt)
#pragma unroll
                    for (int nt = 0; nt < 2; ++nt) {
                        mma16816(acc[g][mt][nt], ah[mt], bhf[nt]);
                        mma16816(acc[g][mt][nt], ah[mt], blf[nt]);
                        mma16816(acc[g][mt][nt], al[mt], bhf[nt]);
                    }
            }
        }
        __syncthreads();
    }

    const int r0 = lane >> 2;
    const int q2 = (lane & 3) * 2;
#pragma unroll
    for (int mt = 0; mt < 2; ++mt) {
#pragma unroll
        for (int nt = 0; nt < 2; ++nt) {
            int col = bh + wn * 16 + nt * 8 + q2;
            float bi0 = g_bleaf[col],        bi1 = g_bleaf[col + 1];
            float bo0 = g_bleaf[512 + col],  bo1 = g_bleaf[512 + col + 1];
            float bu0 = g_bleaf[1024 + col], bu1 = g_bleaf[1024 + col + 1];
#pragma unroll
            for (int hf = 0; hf < 2; ++hf) {
                int row = bm + wm * 32 + mt * 16 + r0 + hf * 8;
                float i0 = sigf(acc[0][mt][nt][hf * 2 + 0] + bi0);
                float i1 = sigf(acc[0][mt][nt][hf * 2 + 1] + bi1);
                float o0 = sigf(acc[1][mt][nt][hf * 2 + 0] + bo0);
                float o1 = sigf(acc[1][mt][nt][hf * 2 + 1] + bo1);
                float u0 = tanhf(acc[2][mt][nt][hf * 2 + 0] + bu0);
                float u1 = tanhf(acc[2][mt][nt][hf * 2 + 1] + bu1);
                float c0 = i0 * u0, c1 = i1 * u1;
                float h0 = o0 * tanhf(c0), h1 = o1 * tanhf(c1);
                size_t gi = (size_t)(4369 + row) * HID + col;
                *(float2*)(g_C + gi) = make_float2(c0, c1);
                *(float2*)(g_H + gi) = make_float2(h0, h1);
                hlf hh0, ll0, hh1, ll1;
                split1(c0, hh0, ll0); split1(c1, hh1, ll1);
                __half2 vh; vh.x = hh0; vh.y = hh1;
                __half2 vl; vl.x = ll0; vl.y = ll1;
                *(__half2*)(g_Ch + gi) = vh;
                *(__half2*)(g_Cl + gi) = vl;
            }
        }
    }
}

// ---------------------------------------------------------------------------
// Split-fp16 GEMM, CTA 128(M) x 256(N), 512 threads / 16 warps,
// warp tile 32x64, BK=32, 3-stage cp.async. N%256==0, K%32==0; M guarded.
// ---------------------------------------------------------------------------
#define TPITCH 80
#define AT_B (128 * TPITCH)            // 10240
#define BT_B (256 * TPITCH)            // 20480
#define STAGE_B (2 * AT_B + 2 * BT_B)  // 61440
#define GSMEM (3 * STAGE_B + 128)

__global__ __launch_bounds__(512)
void gemm_split(const hlf* __restrict__ Ah, const hlf* __restrict__ Al,
                const hlf* __restrict__ Bh, const hlf* __restrict__ Bl,
                float* __restrict__ C, const float* __restrict__ bias,
                int M, int N, int K) {
    extern __shared__ char smem_raw[];
    const uint32_t sbase = (smem_u32(smem_raw) + 127) & ~127u;

    const int tid  = threadIdx.x;
    const int lane = tid & 31;
    const int wid  = tid >> 5;          // 0..15
    const int wm   = wid >> 2;          // 0..3 (M slices of 32)
    const int wn   = wid & 3;           // 0..3 (N slices of 64)
    const int bm   = blockIdx.y * 128;
    const int bn   = blockIdx.x * 256;
    const int NC   = K >> 5;

    const int ag = lane >> 3, ai = lane & 7;
    const int a_row = ai + (ag & 1) * 8;
    const int a_kb  = (ag >> 1) * 16;
    const int b_row = lane & 7;
    const int b_kb  = ((lane >> 3) & 1) * 16;

    float acc[2][8][4];
#pragma unroll
    for (int mt = 0; mt < 2; mt++)
#pragma unroll
        for (int nt = 0; nt < 8; nt++)
#pragma unroll
            for (int j = 0; j < 4; j++) acc[mt][nt][j] = 0.f;

    auto load_chunk = [&](int c, int s) {
        const uint32_t sb = sbase + s * STAGE_B;
        const int k0 = c << 5;
        {   // A: 128 rows x 4 chunks = 512 = 1/thread/tile
            int row = tid >> 2, cb = tid & 3;
            int ar = bm + row; if (ar > M - 1) ar = M - 1;
            size_t aoff = (size_t)ar * K + k0 + cb * 8;
            uint32_t so = row * TPITCH + cb * 16;
            cp16(sb + so,        Ah + aoff);
            cp16(sb + AT_B + so, Al + aoff);
        }
#pragma unroll
        for (int i = 0; i < 2; ++i) {   // B: 256 rows x 4 = 1024 = 2/thread/tile
            int p = tid + i * 512;
            int row = p >> 2, cb = p & 3;
            size_t boff = (size_t)(bn + row) * K + k0 + cb * 8;
            uint32_t so = row * TPITCH + cb * 16;
            cp16(sb + 2 * AT_B + so,        Bh + boff);
            cp16(sb + 2 * AT_B + BT_B + so, Bl + boff);
        }
        CP_COMMIT();
    };

    load_chunk(0, 0);
    if (NC > 1) load_chunk(1, 1);

    for (int c = 0; c < NC; ++c) {
        if (c + 2 < NC) load_chunk(c + 2, (c + 2) % 3);

        if (c + 2 < NC)      asm volatile("cp.async.wait_group 2;" ::: "memory");
        else if (c + 1 < NC) asm volatile("cp.async.wait_group 1;" ::: "memory");
        else                 asm volatile("cp.async.wait_group 0;" ::: "memory");
        __syncthreads();

        const uint32_t sb  = sbase + (c % 3) * STAGE_B;
        const uint32_t tAh = sb,            tAl = sb + AT_B;
        const uint32_t tBh = sb + 2 * AT_B, tBl = sb + 2 * AT_B + BT_B;

#pragma unroll
        for (int ks = 0; ks < 2; ++ks) {
            const int kb = ks * 32;
            uint32_t ah[2][4], al[2][4];
#pragma unroll
            for (int mt = 0; mt < 2; ++mt) {
                uint32_t ro = (wm * 32 + mt * 16 + a_row) * TPITCH + a_kb + kb;
                ldsm4(ah[mt], tAh + ro);
                ldsm4(al[mt], tAl + ro);
            }
#pragma unroll
            for (int nt = 0; nt < 8; ++nt) {
                uint32_t ro = (wn * 64 + nt * 8 + b_row) * TPITCH + b_kb + kb;
                uint32_t bhf[2], blf[2];
                ldsm2(bhf, tBh + ro);
                ldsm2(blf, tBl + ro);
#pragma unroll
                for (int mt = 0; mt < 2; ++mt) {
                    mma16816(acc[mt][nt], ah[mt], bhf);
                    mma16816(acc[mt][nt], ah[mt], blf);
                    mma16816(acc[mt][nt], al[mt], bhf);
                }
            }
        }
        __syncthreads();
    }

    const int r0 = lane >> 2;
    const int q2 = (lane & 3) * 2;
#pragma unroll
    for (int mt = 0; mt < 2; ++mt) {
        int row = bm + wm * 32 + mt * 16 + r0;
#pragma unroll
        for (int nt = 0; nt < 8; ++nt) {
            int col = bn + wn * 64 + nt * 8 + q2;
            float bx = 0.f, by = 0.f;
            if (bias) { bx = bias[col]; by = bias[col + 1]; }
            if (row < M)
                *(float2*)(C + (size_t)row * N + col) =
                    make_float2(acc[mt][nt][0] + bx, acc[mt][nt][1] + by);
            if (row + 8 < M)
                *(float2*)(C + (size_t)(row + 8) * N + col) =
                    make_float2(acc[mt][nt][2] + bx, acc[mt][nt][3] + by);
        }
    }
}

// ---------------------------------------------------------------------------
// Split-fp16 GEMM, CTA 64x64 (small M tail). 128 threads, 4 warps 32x32.
// ---------------------------------------------------------------------------
#define G64_T (64 * TPITCH)
#define G64_STAGE (4 * G64_T)
#define G64_SMEM (3 * G64_STAGE + 128)

__global__ __launch_bounds__(128)
void gemm_split64(const hlf* __restrict__ Ah, const hlf* __restrict__ Al,
                  const hlf* __restrict__ Bh, const hlf* __restrict__ Bl,
                  float* __restrict__ C, const float* __restrict__ bias,
                  int M, int N, int K) {
    extern __shared__ char smem_raw[];
    const uint32_t sbase = (smem_u32(smem_raw) + 127) & ~127u;

    const int tid  = threadIdx.x;
    const int lane = tid & 31;
    const int wid  = tid >> 5;
    const int wm   = wid >> 1;
    const int wn   = wid & 1;
    const int bm   = blockIdx.y * 64;
    const int bn   = blockIdx.x * 64;
    const int NC   = K >> 5;

    const int ag = lane >> 3, ai = lane & 7;
    const int a_row = ai + (ag & 1) * 8;
    const int a_kb  = (ag >> 1) * 16;
    const int b_row = lane & 7;
    const int b_kb  = ((lane >> 3) & 1) * 16;

    float acc[2][4][4];
#pragma unroll
    for (int mt = 0; mt < 2; mt++)
#pragma unroll
        for (int nt = 0; nt < 4; nt++)
#pragma unroll
            for (int j = 0; j < 4; j++) acc[mt][nt][j] = 0.f;

    auto load_chunk = [&](int c, int s) {
        const uint32_t sb = sbase + s * G64_STAGE;
        const int k0 = c << 5;
#pragma unroll
        for (int it = 0; it < 2; ++it) {
            int idx = tid + it * 128;
            int row = idx >> 2, cb = idx & 3;
            int ar = bm + row; if (ar > M - 1) ar = M - 1;
            size_t aoff = (size_t)ar * K + k0 + cb * 8;
            size_t boff = (size_t)(bn + row) * K + k0 + cb * 8;
            uint32_t so = row * TPITCH + cb * 16;
            cp16(sb + so,             Ah + aoff);
            cp16(sb + G64_T + so,     Al + aoff);
            cp16(sb + 2 * G64_T + so, Bh + boff);
            cp16(sb + 3 * G64_T + so, Bl + boff);
        }
        CP_COMMIT();
    };

    load_chunk(0, 0);
    if (NC > 1) load_chunk(1, 1);

    for (int c = 0; c < NC; ++c) {
        if (c + 2 < NC) load_chunk(c + 2, (c + 2) % 3);

        if (c + 2 < NC)      asm volatile("cp.async.wait_group 2;" ::: "memory");
        else if (c + 1 < NC) asm volatile("cp.async.wait_group 1;" ::: "memory");
        else                 asm volatile("cp.async.wait_group 0;" ::: "memory");
        __syncthreads();

        const uint32_t sb  = sbase + (c % 3) * G64_STAGE;
        const uint32_t tAh = sb,             tAl = sb + G64_T;
        const uint32_t tBh = sb + 2 * G64_T, tBl = sb + 3 * G64_T;

#pragma unroll
        for (int ks = 0; ks < 2; ++ks) {
            const int kb = ks * 32;
            uint32_t ah[2][4], al[2][4], bhf[4][2], blf[4][2];
#pragma unroll
            for (int mt = 0; mt < 2; ++mt) {
                uint32_t ro = (wm * 32 + mt * 16 + a_row) * TPITCH + a_kb + kb;
                ldsm4(ah[mt], tAh + ro);
                ldsm4(al[mt], tAl + ro);
            }
#pragma unroll
            for (int nt = 0; nt < 4; ++nt) {
                uint32_t ro = (wn * 32 + nt * 8 + b_row) * TPITCH + b_kb + kb;
                ldsm2(bhf[nt], tBh + ro);
                ldsm2(blf[nt], tBl + ro);
            }
#pragma unroll
            for (int mt = 0; mt < 2; ++mt)
#pragma unroll
                for (int nt = 0; nt < 4; ++nt) {
                    mma16816(acc[mt][nt], ah[mt], bhf[nt]);
                    mma16816(acc[mt][nt], ah[mt], blf[nt]);
                    mma16816(acc[mt][nt], al[mt], bhf[nt]);
                }
        }
        __syncthreads();
    }

    const int r0 = lane >> 2;
    const int q2 = (lane & 3) * 2;
#pragma unroll
    for (int mt = 0; mt < 2; ++mt) {
        int row = bm + wm * 32 + mt * 16 + r0;
#pragma unroll
        for (int nt = 0; nt < 4; ++nt) {
            int col = bn + wn * 32 + nt * 8 + q2;
            float bx = 0.f, by = 0.f;
            if (bias) { bx = bias[col]; by = bias[col + 1]; }
            if (row < M)
                *(float2*)(C + (size_t)row * N + col) =
                    make_float2(acc[mt][nt][0] + bx, acc[mt][nt][1] + by);
            if (row + 8 < M)
                *(float2*)(C + (size_t)(row + 8) * N + col) =
                    make_float2(acc[mt][nt][2] + bx, acc[mt][nt][3] + by);
        }
    }
}

// ---------------------------------------------------------------------------
// Weight packing (fp32 -> split fp16) + biases
// ---------------------------------------------------------------------------
__global__ void pack_weights(const float* __restrict__ wi_w, const float* __restrict__ wi_b,
                             const float* __restrict__ wf_w, const float* __restrict__ wf_b,
                             const float* __restrict__ wo_w, const float* __restrict__ wo_b,
                             const float* __restrict__ wu_w, const float* __restrict__ wu_b) {
    int idx = blockIdx.x * blockDim.x + threadIdx.x;

    if (idx < 2048 * 1024) {
        int r = idx >> 10, k = idx & 1023;
        float v;
        if      (r <  512) v = wi_w[r * 1024 + k];
        else if (r < 1024) v = wo_w[(r -  512) * 1024 + k];
        else if (r < 1536) v = wu_w[(r - 1024) * 1024 + k];
        else               v = (k < 512) ? wf_w[(r - 1536) * 1024 + k] : 0.f;
        split1(v, g_Wnh[idx], g_Wnl[idx]);
    }
    if (idx < 1536 * 512) {
        int r = idx >> 9, k = idx & 511;
        float v;
        if      (r <  512) v = wi_w[r * 1024 + k];
        else if (r < 1024) v = wo_w[(r -  512) * 1024 + k];
        else               v = wu_w[(r - 1024) * 1024 + k];
        split1(v, g_Wlh[idx], g_Wll[idx]);
    }
    if (idx < 512 * 512) {
        int r = idx >> 9, k = idx & 511;
        split1(wf_w[r * 1024 + 512 + k], g_Wfhh[idx], g_Wfhl[idx]);
    }
    if (idx < 1536)
        g_bleaf[idx] = (idx < 512) ? wi_b[idx] : (idx < 1024) ? wo_b[idx - 512] : wu_b[idx - 1024];
    if (idx < 2048)
        g_bnode[idx] = (idx <  512) ? wi_b[idx]
                     : (idx < 1024) ? wo_b[idx -  512]
                     : (idx < 1536) ? wu_b[idx - 1024] : wf_b[idx - 1536];
}

// fp32 -> split fp16, 4 elems/thread
__global__ void split4(const float* __restrict__ src, hlf* __restrict__ h,
                       hlf* __restrict__ l, int n4) {
    int i = blockIdx.x * blockDim.x + threadIdx.x;
    if (i >= n4) return;
    float4 v = ((const float4*)src)[i];
    hlf hh[4], ll[4];
    split1(v.x, hh[0], ll[0]); split1(v.y, hh[1], ll[1]);
    split1(v.z, hh[2], ll[2]); split1(v.w, hh[3], ll[3]);
    ((uint2*)h)[i] = *(uint2*)hh;
    ((uint2*)l)[i] = *(uint2*)ll;
}

// ---------------------------------------------------------------------------
// Elementwise stages (float4 vectorized)
// ---------------------------------------------------------------------------
__global__ void concat_xh4(const float* __restrict__ x, int off_d, int off_c, int n) {
    int idx = blockIdx.x * blockDim.x + threadIdx.x;
    if (idx >= n * 256) return;
    int r = idx >> 8, c4 = (idx & 255) * 4;
    float4 v;
    if (c4 < 512) {
        v = *(const float4*)(x + (size_t)(off_d + r) * IN_DIM + c4);
    } else {
        int hc = c4 - 512;
        size_t base = (size_t)(off_c + r * 16) * HID + hc;
        v = make_float4(0.f, 0.f, 0.f, 0.f);
#pragma unroll
        for (int k = 0; k < 16; k++) {
            float4 t = *(const float4*)(g_H + base + k * HID);
            v.x += t.x; v.y += t.y; v.z += t.z; v.w += t.w;
        }
    }
    hlf hh[4], ll[4];
    split1(v.x, hh[0], ll[0]); split1(v.y, hh[1], ll[1]);
    split1(v.z, hh[2], ll[2]); split1(v.w, hh[3], ll[3]);
    size_t o = (size_t)r * 1024 + c4;
    *(uint2*)(g_XHh + o) = *(uint2*)hh;
    *(uint2*)(g_XHl + o) = *(uint2*)ll;
}

__global__ void node_epilogue4(int off_d, int off_c, int n) {
    int idx = blockIdx.x * blockDim.x + threadIdx.x;
    if (idx >= n * 128) return;
    int r = idx >> 7, h4 = (idx & 127) * 4;
    const float* g = g_G + (size_t)r * 2048;
    float4 gi = *(const float4*)(g + h4);
    float4 go = *(const float4*)(g + 512 + h4);
    float4 gu = *(const float4*)(g + 1024 + h4);
    float4 gf = *(const float4*)(g + 1536 + h4);
    float a0 = sigf(gi.x) * tanhf(gu.x);
    float a1 = sigf(gi.y) * tanhf(gu.y);
    float a2 = sigf(gi.z) * tanhf(gu.z);
    float a3 = sigf(gi.w) * tanhf(gu.w);
    size_t cb = (size_t)(off_c + r * 16) * HID + h4;
#pragma unroll
    for (int k = 0; k < 16; k++) {
        float4 fh = *(const float4*)(g_FH + cb + k * HID);
        float4 cc = *(const float4*)(g_C  + cb + k * HID);
        a0 += sigf(gf.x + fh.x) * cc.x;
        a1 += sigf(gf.y + fh.y) * cc.y;
        a2 += sigf(gf.z + fh.z) * cc.z;
        a3 += sigf(gf.w + fh.w) * cc.w;
    }
    size_t gidx = (size_t)(off_d + r) * HID + h4;
    *(float4*)(g_C + gidx) = make_float4(a0, a1, a2, a3);
    float4 hv = make_float4(sigf(go.x) * tanhf(a0), sigf(go.y) * tanhf(a1),
                            sigf(go.z) * tanhf(a2), sigf(go.w) * tanhf(a3));
    *(float4*)(g_H + gidx) = hv;
    hlf hh[4], ll[4];
    split1(a0, hh[0], ll[0]); split1(a1, hh[1], ll[1]);
    split1(a2, hh[2], ll[2]); split1(a3, hh[3], ll[3]);
    *(uint2*)(g_Ch + gidx) = *(uint2*)hh;
    *(uint2*)(g_Cl + gidx) = *(uint2*)ll;
}

__global__ void writeout(float* __restrict__ out) {
    int idx = blockIdx.x * blockDim.x + threadIdx.x;
    if (idx < 512)       out[idx] = g_H[idx];
    else if (idx < 1024) out[idx] = g_C[idx - 512];
}

// ---------------------------------------------------------------------------
// Launch
// ---------------------------------------------------------------------------
static void launch_gemm(const hlf* Ah, const hlf* Al, const hlf* Bh, const hlf* Bl,
                        float* C, const float* bias, int M, int N, int K) {
    if (M >= 1024) {
        dim3 grid(N / 256, (M + 127) / 128);
        gemm_split<<<grid, 512, GSMEM>>>(Ah, Al, Bh, Bl, C, bias, M, N, K);
    } else {
        dim3 grid(N / 64, (M + 63) / 64);
        gemm_split64<<<grid, 128, G64_SMEM>>>(Ah, Al, Bh, Bl, C, bias, M, N, K);
    }
}

extern "C" void kernel_launch(void* const* d_in, const int* in_sizes, int n_in,
                              void* d_out, int out_size) {
    const float* x    = (const float*)d_in[0];
    const float* wi_w = (const float*)d_in[1];
    const float* wi_b = (const float*)d_in[2];
    const float* wf_w = (const float*)d_in[3];
    const float* wf_b = (const float*)d_in[4];
    const float* wo_w = (const float*)d_in[5];
    const float* wo_b = (const float*)d_in[6];
    const float* wu_w = (const float*)d_in[7];
    const float* wu_b = (const float*)d_in[8];
    float* out = (float*)d_out;

    cudaFuncSetAttribute(gemm_split,   cudaFuncAttributeMaxDynamicSharedMemorySize, GSMEM);
    cudaFuncSetAttribute(gemm_split64, cudaFuncAttributeMaxDynamicSharedMemorySize, G64_SMEM);
    cudaFuncSetAttribute(leaf_fused,   cudaFuncAttributeMaxDynamicSharedMemorySize, LF_SMEM);

    float *pC, *pFH, *pG, *pbn;
    hlf *pXh, *pXl, *pCh, *pCl, *pXHh, *pXHl, *pWnh, *pWnl, *pWfhh, *pWfhl;
    cudaGetSymbolAddress((void**)&pC,    g_C);
    cudaGetSymbolAddress((void**)&pFH,   g_FH);
    cudaGetSymbolAddress((void**)&pG,    g_G);
    cudaGetSymbolAddress((void**)&pbn,   g_bnode);
    cudaGetSymbolAddress((void**)&pXh,   g_Xh);
    cudaGetSymbolAddress((void**)&pXl,   g_Xl);
    cudaGetSymbolAddress((void**)&pCh,   g_Ch);
    cudaGetSymbolAddress((void**)&pCl,   g_Cl);
    cudaGetSymbolAddress((void**)&pXHh,  g_XHh);
    cudaGetSymbolAddress((void**)&pXHl,  g_XHl);
    cudaGetSymbolAddress((void**)&pWnh,  g_Wnh);
    cudaGetSymbolAddress((void**)&pWnl,  g_Wnl);
    cudaGetSymbolAddress((void**)&pWfhh, g_Wfhh);
    cudaGetSymbolAddress((void**)&pWfhl, g_Wfhl);

    static const int offs[6]  = {0, 1, 17, 273, 4369, 69905};
    static const int sizes[5] = {1, 16, 256, 4096, 65536};

    // 1) weights -> split fp16
    pack_weights<<<(2048 * 1024 + 255) / 256, 256>>>(wi_w, wi_b, wf_w, wf_b,
                                                     wo_w, wo_b, wu_w, wu_b);
    // 2) leaf x -> split fp16
    split4<<<(NLEAF * IN_DIM / 4 + 255) / 256, 256>>>(x + (size_t)offs[4] * IN_DIM,
                                                      pXh, pXl, NLEAF * IN_DIM / 4);
    // 3) fused leaf gates (writes C,H,Ch,Cl), then FH GEMM
    {
        dim3 grid(HID / 64, NLEAF / 128);
        leaf_fused<<<grid, 512, LF_SMEM>>>(pXh, pXl);
    }
    launch_gemm(pCh + (size_t)offs[4] * HID, pCl + (size_t)offs[4] * HID,
                pWfhh, pWfhl, pFH + (size_t)offs[4] * HID, nullptr, NLEAF, 512, 512);

    // 4) internal levels, bottom-up
    for (int d = 3; d >= 0; d--) {
        int n = sizes[d];
        concat_xh4<<<(n * 256 + 255) / 256, 256>>>(x, offs[d], offs[d + 1], n);
        launch_gemm(pXHh, pXHl, pWnh, pWnl, pG, pbn, n, 2048, 1024);
        node_epilogue4<<<(n * 128 + 255) / 256, 256>>>(offs[d], offs[d + 1], n);
        if (d > 0)
            launch_gemm(pCh + (size_t)offs[d] * HID, pCl + (size_t)offs[d] * HID,
                        pWfhh, pWfhl, pFH + (size_t)offs[d] * HID, nullptr, n, 512, 512);
    }

    // 5) output: H[0] then C[0]
    writeout<<<4, 256>>>(out);
}